// round 3
// baseline (speedup 1.0000x reference)
#include <cuda_runtime.h>
#include <cuda_bf16.h>
#include <cstdint>

// Problem constants
#define N_ROWS   131072      // B*H*W = 32*64*64
#define DDIM     64
#define KCB      1024
#define DECAY    0.99f
#define ONEMD    0.01f
#define EPS      1e-5f
#define DELTA    0.75f       // candidate margin (>= 2x worst-case tf32-hi error)

#define KT       64          // codebook columns per smem tile
#define NTILES   (KCB / KT)  // 16
#define TILE_HI  (8 * KT * 8)   // ksteps * n * 8 = 4096 floats = 16KB
#define NCHUNKS  (N_ROWS / 128) // 1024
#define GRID_A   296

// Output layout
#define OFF_Q    0
#define OFF_LOSS (N_ROWS*DDIM)
#define OFF_NCB  (OFF_LOSS + 1)
#define OFF_ECS  (OFF_NCB + DDIM*KCB)
#define OFF_EIS  (OFF_ECS + KCB)

// Scratch
__device__ int   g_idx[N_ROWS];
__device__ float g_counts[KCB];
__device__ float g_isum[KCB * DDIM];   // [k][d]
__device__ float g_l2cb[KCB];
__device__ float g_ncbT[KCB * DDIM];   // [k][d]
__device__ float g_loss[1];
__device__ float g_cbhi[KCB * DDIM];   // tile-ordered tf32-hi image (256KB)

// ---------------------------------------------------------------------------
__device__ __forceinline__ uint32_t tf32_hi(float x) {
    uint32_t hb;
    asm("cvt.rna.tf32.f32 %0, %1;" : "=r"(hb) : "f"(x));
    return hb;
}

__device__ __forceinline__ void mma8(float c[4], const uint32_t a[4],
                                     uint32_t b0, uint32_t b1) {
    asm volatile(
        "mma.sync.aligned.m16n8k8.row.col.f32.tf32.tf32.f32 "
        "{%0,%1,%2,%3},{%4,%5,%6,%7},{%8,%9},{%0,%1,%2,%3};"
        : "+f"(c[0]), "+f"(c[1]), "+f"(c[2]), "+f"(c[3])
        : "r"(a[0]), "r"(a[1]), "r"(a[2]), "r"(a[3]), "r"(b0), "r"(b1));
}

__device__ __forceinline__ void cp_async16(uint32_t smem_dst, const void* gsrc) {
    asm volatile("cp.async.cg.shared.global [%0], [%1], 16;"
                 :: "r"(smem_dst), "l"(gsrc));
}

// sorted top-4 insertion (ascending)
__device__ __forceinline__ void top4_ins(float s, int k, float v[4], int id[4]) {
    if (s < v[3]) {
        if (s < v[1]) {
            v[3] = v[2]; id[3] = id[2];
            v[2] = v[1]; id[2] = id[1];
            if (s < v[0]) { v[1] = v[0]; id[1] = id[0]; v[0] = s; id[0] = k; }
            else          { v[1] = s; id[1] = k; }
        } else {
            if (s < v[2]) { v[3] = v[2]; id[3] = id[2]; v[2] = s; id[2] = k; }
            else          { v[3] = s; id[3] = k; }
        }
    }
}

// ---------------------------------------------------------------------------
// Kernel 0: zero scratch, ||c_k||^2, tile-ordered tf32-hi image
// ---------------------------------------------------------------------------
__global__ void k_init(const float* __restrict__ cb) {
    int i = blockIdx.x * blockDim.x + threadIdx.x;   // 0..65535
    int n = i & (KCB - 1);
    int d = i >> 10;

    g_isum[i] = 0.0f;

    float x = cb[d * KCB + n];
    int tt = n >> 6, nl = n & 63;
    int ks = d >> 3, dd = d & 7;
    int t = dd & 3, hh = dd >> 2;
    g_cbhi[tt * TILE_HI + (ks * KT + nl) * 8 + t * 2 + hh] =
        __uint_as_float(tf32_hi(x));

    if (i < KCB) {
        g_counts[i] = 0.0f;
        float s = 0.0f;
        #pragma unroll
        for (int dj = 0; dj < DDIM; ++dj) {
            float c = cb[dj * KCB + i];
            s = fmaf(c, c, s);
        }
        g_l2cb[i] = s;
    }
    if (i == 0) g_loss[0] = 0.0f;
}

// ---------------------------------------------------------------------------
// Kernel A: approx tensor argmin (tf32 hi) + exact fp32 rescore + scatter
// Persistent grid; 8 warps/block, 16 rows/warp -> 128 rows/chunk.
// ---------------------------------------------------------------------------
__global__ __launch_bounds__(256, 2) void k_argmin_scatter(
        const float* __restrict__ X, const float* __restrict__ CB)
{
    __shared__ float s_l2[KCB];
    __shared__ float s_b[2 * TILE_HI];

    const int tid  = threadIdx.x;
    const int wid  = tid >> 5;
    const int lane = tid & 31;
    const int g    = lane >> 2;   // row group 0..7
    const int t    = lane & 3;

    for (int i = tid; i < KCB; i += 256) s_l2[i] = g_l2cb[i];

    const uint32_t sb_base = (uint32_t)__cvta_generic_to_shared(s_b);
    auto stage = [&](int tt, int b) {
        const float4* src = reinterpret_cast<const float4*>(g_cbhi + tt * TILE_HI);
        uint32_t dst = sb_base + (uint32_t)(b * TILE_HI * 4);
        #pragma unroll
        for (int j = 0; j < TILE_HI / 4 / 256; ++j) {   // 4 per thread
            int e = tid + j * 256;
            cp_async16(dst + e * 16, src + e);
        }
        asm volatile("cp.async.commit_group;");
    };

    // exact rescore of one row's candidate set; returns argmin idx (all lanes)
    auto rescore_row = [&](int row, const float v[4], const int id[4],
                           float m) -> int {
        float bestd = __int_as_float(0x7f800000);
        int   bestk = 0x7fffffff;
        if (v[0] <= m + DELTA) {
            const float4* xr = reinterpret_cast<const float4*>(X + (size_t)row * DDIM);
            // exact ||x||^2, 4 accumulators (same association as the fp32 kernel)
            float l0 = 0.f, l1 = 0.f, l2 = 0.f, l3 = 0.f;
            #pragma unroll
            for (int j = 0; j < 16; ++j) {
                float4 xv = xr[j];
                l0 = fmaf(xv.x, xv.x, l0);
                l1 = fmaf(xv.y, xv.y, l1);
                l2 = fmaf(xv.z, xv.z, l2);
                l3 = fmaf(xv.w, xv.w, l3);
            }
            float l2x = (l0 + l1) + (l2 + l3);
            #pragma unroll
            for (int j = 0; j < 4; ++j) {
                if (v[j] > m + DELTA) break;
                int k = id[j];
                float a0 = 0.f, a1 = 0.f, a2 = 0.f, a3 = 0.f;
                #pragma unroll
                for (int jj = 0; jj < 16; ++jj) {
                    float4 xv = xr[jj];
                    a0 = fmaf(xv.x, CB[(4 * jj + 0) * KCB + k], a0);
                    a1 = fmaf(xv.y, CB[(4 * jj + 1) * KCB + k], a1);
                    a2 = fmaf(xv.z, CB[(4 * jj + 2) * KCB + k], a2);
                    a3 = fmaf(xv.w, CB[(4 * jj + 3) * KCB + k], a3);
                }
                float dot = (a0 + a1) + (a2 + a3);
                float d = fmaf(-2.f, dot, l2x) + s_l2[k];
                if (d < bestd || (d == bestd && k < bestk)) { bestd = d; bestk = k; }
            }
        }
        #pragma unroll
        for (int off = 1; off < 4; off <<= 1) {
            float od = __shfl_xor_sync(0xffffffffu, bestd, off);
            int   ok = __shfl_xor_sync(0xffffffffu, bestk, off);
            if (od < bestd || (od == bestd && ok < bestk)) { bestd = od; bestk = ok; }
        }
        return bestk;
    };

    for (int chunk = blockIdx.x; chunk < NCHUNKS; chunk += GRID_A) {
        const int base_row = chunk * 128 + wid * 16;
        const int r0 = base_row + g;
        const int r1 = r0 + 8;

        // A fragments (hi only)
        uint32_t Ah[8][4];
        #pragma unroll
        for (int ks = 0; ks < 8; ++ks) {
            Ah[ks][0] = tf32_hi(X[(size_t)r0 * DDIM + ks * 8 + t]);
            Ah[ks][1] = tf32_hi(X[(size_t)r1 * DDIM + ks * 8 + t]);
            Ah[ks][2] = tf32_hi(X[(size_t)r0 * DDIM + ks * 8 + t + 4]);
            Ah[ks][3] = tf32_hi(X[(size_t)r1 * DDIM + ks * 8 + t + 4]);
        }

        stage(0, 0);
        stage(1, 1);

        const float INF = __int_as_float(0x7f800000);
        float v0[4] = {INF, INF, INF, INF}, v1[4] = {INF, INF, INF, INF};
        int   i0[4] = {0, 0, 0, 0},        i1[4] = {0, 0, 0, 0};

        for (int tt = 0; tt < NTILES; ++tt) {
            if (tt == NTILES - 1) { asm volatile("cp.async.wait_group 0;"); }
            else                  { asm volatile("cp.async.wait_group 1;"); }
            __syncthreads();

            const float* sb = s_b + (tt & 1) * TILE_HI;

            #pragma unroll
            for (int sp = 0; sp < 4; ++sp) {
                const int nl0 = (2 * sp + 0) * 8 + g;
                const int nl1 = (2 * sp + 1) * 8 + g;
                float c0[4] = {0.f, 0.f, 0.f, 0.f};
                float c1[4] = {0.f, 0.f, 0.f, 0.f};

                #pragma unroll
                for (int ks = 0; ks < 8; ++ks) {
                    float2 b0 = *reinterpret_cast<const float2*>(
                        &sb[(ks * KT + nl0) * 8 + 2 * t]);
                    float2 b1 = *reinterpret_cast<const float2*>(
                        &sb[(ks * KT + nl1) * 8 + 2 * t]);
                    mma8(c0, Ah[ks], __float_as_uint(b0.x), __float_as_uint(b0.y));
                    mma8(c1, Ah[ks], __float_as_uint(b1.x), __float_as_uint(b1.y));
                }

                {
                    const int col0 = tt * KT + (2 * sp + 0) * 8 + 2 * t;
                    float2 l2p = *reinterpret_cast<const float2*>(&s_l2[col0]);
                    top4_ins(fmaf(-2.f, c0[0], l2p.x), col0,     v0, i0);
                    top4_ins(fmaf(-2.f, c0[1], l2p.y), col0 + 1, v0, i0);
                    top4_ins(fmaf(-2.f, c0[2], l2p.x), col0,     v1, i1);
                    top4_ins(fmaf(-2.f, c0[3], l2p.y), col0 + 1, v1, i1);
                }
                {
                    const int col1 = tt * KT + (2 * sp + 1) * 8 + 2 * t;
                    float2 l2p = *reinterpret_cast<const float2*>(&s_l2[col1]);
                    top4_ins(fmaf(-2.f, c1[0], l2p.x), col1,     v0, i0);
                    top4_ins(fmaf(-2.f, c1[1], l2p.y), col1 + 1, v0, i0);
                    top4_ins(fmaf(-2.f, c1[2], l2p.x), col1,     v1, i1);
                    top4_ins(fmaf(-2.f, c1[3], l2p.y), col1 + 1, v1, i1);
                }
            }

            __syncthreads();
            if (tt + 2 < NTILES) stage(tt + 2, tt & 1);
        }

        // approx min over the quad
        float m0 = v0[0], m1 = v1[0];
        #pragma unroll
        for (int off = 1; off < 4; off <<= 1) {
            m0 = fminf(m0, __shfl_xor_sync(0xffffffffu, m0, off));
            m1 = fminf(m1, __shfl_xor_sync(0xffffffffu, m1, off));
        }

        // exact rescore of candidates
        int bi0 = rescore_row(r0, v0, i0, m0);
        int bi1 = rescore_row(r1, v1, i1, m1);

        if (t == 0) {
            g_idx[r0] = bi0;
            atomicAdd(&g_counts[bi0], 1.0f);
            g_idx[r1] = bi1;
            atomicAdd(&g_counts[bi1], 1.0f);
        }

        // scatter input sums: 16 rows x 64 dims per warp
        #pragma unroll
        for (int r = 0; r < 16; ++r) {
            int src_lane = (r & 7) * 4;
            int idx = (r < 8) ? __shfl_sync(0xffffffffu, bi0, src_lane)
                              : __shfl_sync(0xffffffffu, bi1, src_lane);
            int row = base_row + r;
            float va = X[(size_t)row * DDIM + lane];
            float vb = X[(size_t)row * DDIM + lane + 32];
            atomicAdd(&g_isum[idx * DDIM + lane], va);
            atomicAdd(&g_isum[idx * DDIM + lane + 32], vb);
        }
    }
}

// ---------------------------------------------------------------------------
// Kernel B: EMA update, normalization, new codebook
// ---------------------------------------------------------------------------
__global__ __launch_bounds__(1024) void k_ema(
        const float* __restrict__ ema_cs,
        const float* __restrict__ ema_eis,
        float* __restrict__ out)
{
    __shared__ float red[1024];
    const int k = threadIdx.x;

    float ne = DECAY * ema_cs[k] + ONEMD * g_counts[k];
    out[OFF_ECS + k] = ne;

    red[k] = ne;
    __syncthreads();
    for (int s = 512; s > 0; s >>= 1) {
        if (k < s) red[k] += red[k + s];
        __syncthreads();
    }
    const float n = red[0];

    const float norm = (ne + EPS) / (n + (float)KCB * EPS);
    const float cs   = norm * n;
    const float inv_cs = 1.0f / cs;

    #pragma unroll
    for (int d = 0; d < DDIM; ++d) {
        float eis = DECAY * ema_eis[d * KCB + k] + ONEMD * g_isum[k * DDIM + d];
        out[OFF_EIS + d * KCB + k] = eis;
        float nc = eis * inv_cs;
        out[OFF_NCB + d * KCB + k] = nc;
        g_ncbT[k * DDIM + d] = nc;
    }
}

// ---------------------------------------------------------------------------
// Kernel C: gather + straight-through + loss (float4 vectorized)
// ---------------------------------------------------------------------------
__global__ __launch_bounds__(256) void k_gather_loss(
        const float* __restrict__ X, float* __restrict__ out)
{
    float acc = 0.0f;
    const int total4 = N_ROWS * DDIM / 4;
    const float4* X4 = reinterpret_cast<const float4*>(X);
    const float4* Q4 = reinterpret_cast<const float4*>(g_ncbT);
    float4* O4 = reinterpret_cast<float4*>(out + OFF_Q);

    for (int e = blockIdx.x * blockDim.x + threadIdx.x; e < total4;
         e += gridDim.x * blockDim.x) {
        int n  = e >> 4;
        int d4 = e & 15;
        float4 q = Q4[(g_idx[n] << 4) | d4];
        float4 x = X4[e];
        float dx = q.x - x.x, dy = q.y - x.y, dz = q.z - x.z, dw = q.w - x.w;
        float4 o;
        o.x = x.x + dx; o.y = x.y + dy; o.z = x.z + dz; o.w = x.w + dw;
        O4[e] = o;
        acc = fmaf(dx, dx, acc);
        acc = fmaf(dy, dy, acc);
        acc = fmaf(dz, dz, acc);
        acc = fmaf(dw, dw, acc);
    }
    #pragma unroll
    for (int o = 16; o > 0; o >>= 1)
        acc += __shfl_down_sync(0xffffffffu, acc, o);
    __shared__ float warpsum[8];
    int lane = threadIdx.x & 31, wid = threadIdx.x >> 5;
    if (lane == 0) warpsum[wid] = acc;
    __syncthreads();
    if (wid == 0) {
        float v = (lane < 8) ? warpsum[lane] : 0.0f;
        #pragma unroll
        for (int o = 4; o > 0; o >>= 1)
            v += __shfl_down_sync(0xffffffffu, v, o);
        if (lane == 0) atomicAdd(g_loss, v);
    }
}

__global__ void k_loss_finalize(float* __restrict__ out) {
    out[OFF_LOSS] = g_loss[0] * (1.0f / (float)(N_ROWS * DDIM));
}

// ---------------------------------------------------------------------------
extern "C" void kernel_launch(void* const* d_in, const int* in_sizes, int n_in,
                              void* d_out, int out_size) {
    const float* X       = (const float*)d_in[0];
    const float* CB      = (const float*)d_in[1];
    const float* EMA_CS  = (const float*)d_in[2];
    const float* EMA_EIS = (const float*)d_in[3];
    float* out = (float*)d_out;

    k_init<<<256, 256>>>(CB);
    k_argmin_scatter<<<GRID_A, 256>>>(X, CB);
    k_ema<<<1, 1024>>>(EMA_CS, EMA_EIS, out);
    k_gather_loss<<<2048, 256>>>(X, out);
    k_loss_finalize<<<1, 1>>>(out);
}

// round 4
// speedup vs baseline: 1.4523x; 1.4523x over previous
#include <cuda_runtime.h>
#include <cuda_bf16.h>
#include <cstdint>

// Problem constants
#define N_ROWS   131072      // B*H*W
#define DDIM     64
#define KCB      1024
#define DECAY    0.99f
#define ONEMD    0.01f
#define EPS      1e-5f
#define DELTA    0.75f       // rescore margin (>= 2x worst-case tf32-hi error)

#define KT       64              // codebook cols per tile
#define NTILES   (KCB / KT)      // 16
#define TILE_HI  (8 * 8 * 64)    // ks * nb * 64 floats = 4096 floats = 16KB
#define ROWS_PER_CHUNK 256
#define NCHUNKS  (N_ROWS / ROWS_PER_CHUNK)   // 512
#define GRID_A   296

// Output layout
#define OFF_Q    0
#define OFF_LOSS (N_ROWS*DDIM)
#define OFF_NCB  (OFF_LOSS + 1)
#define OFF_ECS  (OFF_NCB + DDIM*KCB)
#define OFF_EIS  (OFF_ECS + KCB)

// Scratch
__device__ int   g_idx[N_ROWS];
__device__ float g_counts[KCB];
__device__ float g_isum[KCB * DDIM];   // [k][d]
__device__ float g_l2cb[KCB];
__device__ float g_invcs[KCB];
__device__ float g_ncbT[KCB * DDIM];   // [k][d]
__device__ float g_loss[1];
__device__ float g_cbhi[KCB * DDIM];   // fragment-major tf32-hi image (256KB)

// ---------------------------------------------------------------------------
__device__ __forceinline__ uint32_t tf32_hi(float x) {
    uint32_t hb;
    asm("cvt.rna.tf32.f32 %0, %1;" : "=r"(hb) : "f"(x));
    return hb;
}

__device__ __forceinline__ void mma8(float c[4], const uint32_t a[4],
                                     uint32_t b0, uint32_t b1) {
    asm volatile(
        "mma.sync.aligned.m16n8k8.row.col.f32.tf32.tf32.f32 "
        "{%0,%1,%2,%3},{%4,%5,%6,%7},{%8,%9},{%0,%1,%2,%3};"
        : "+f"(c[0]), "+f"(c[1]), "+f"(c[2]), "+f"(c[3])
        : "r"(a[0]), "r"(a[1]), "r"(a[2]), "r"(a[3]), "r"(b0), "r"(b1));
}

__device__ __forceinline__ void cp_async16(uint32_t smem_dst, const void* gsrc) {
    asm volatile("cp.async.cg.shared.global [%0], [%1], 16;"
                 :: "r"(smem_dst), "l"(gsrc));
}

// sorted top-4 insertion (ascending)
__device__ __forceinline__ void top4_ins(float s, int k, float v[4], int id[4]) {
    if (s < v[3]) {
        if (s < v[1]) {
            v[3] = v[2]; id[3] = id[2];
            v[2] = v[1]; id[2] = id[1];
            if (s < v[0]) { v[1] = v[0]; id[1] = id[0]; v[0] = s; id[0] = k; }
            else          { v[1] = s; id[1] = k; }
        } else {
            if (s < v[2]) { v[3] = v[2]; id[3] = id[2]; v[2] = s; id[2] = k; }
            else          { v[3] = s; id[3] = k; }
        }
    }
}

// ---------------------------------------------------------------------------
// Kernel 0: zero scratch, ||c_k||^2, fragment-major tf32-hi image
// frag float index within tile: (ks*8+nb)*64 + lane*2 + h, lane = g*4 + t,
// value = CB[d = ks*8 + (h ? t+4 : t)][n = tt*64 + nb*8 + g]
// ---------------------------------------------------------------------------
__global__ void k_init(const float* __restrict__ cb) {
    int i = blockIdx.x * blockDim.x + threadIdx.x;   // 0..65535
    int n = i & (KCB - 1);
    int d = i >> 10;

    g_isum[i] = 0.0f;

    float x = cb[d * KCB + n];
    int tt = n >> 6, nl = n & 63;
    int nb = nl >> 3, g = nl & 7;
    int ks = d >> 3, dd = d & 7;
    int t = dd & 3, h = dd >> 2;
    g_cbhi[tt * TILE_HI + (ks * 8 + nb) * 64 + (g * 4 + t) * 2 + h] =
        __uint_as_float(tf32_hi(x));

    if (i < KCB) {
        g_counts[i] = 0.0f;
        float s = 0.0f;
        #pragma unroll
        for (int dj = 0; dj < DDIM; ++dj) {
            float c = cb[dj * KCB + i];
            s = fmaf(c, c, s);
        }
        g_l2cb[i] = s;
    }
    if (i == 0) g_loss[0] = 0.0f;
}

// ---------------------------------------------------------------------------
// Kernel A: approx tensor argmin (tf32 hi) + exact fp32 rescore + scatter.
// 8 warps x 32 rows = 256 rows/chunk. 3-deep cp.async pipeline, 1 barrier/tile.
// ---------------------------------------------------------------------------
extern __shared__ float s_dyn[];

__global__ __launch_bounds__(256, 2) void k_argmin_scatter(
        const float* __restrict__ X, const float* __restrict__ CB)
{
    float* s_l2 = s_dyn;              // 1024 floats
    float* s_b  = s_dyn + KCB;        // 3 * TILE_HI

    const int tid  = threadIdx.x;
    const int wid  = tid >> 5;
    const int lane = tid & 31;
    const int g    = lane >> 2;
    const int t    = lane & 3;

    for (int i = tid; i < KCB; i += 256) s_l2[i] = g_l2cb[i];

    const uint32_t sb_base = (uint32_t)__cvta_generic_to_shared(s_b);
    auto stage = [&](int tt) {
        const float4* src = reinterpret_cast<const float4*>(g_cbhi + tt * TILE_HI);
        uint32_t dst = sb_base + (uint32_t)((tt % 3) * TILE_HI * 4);
        #pragma unroll
        for (int j = 0; j < TILE_HI / 4 / 256; ++j) {   // 4 per thread
            int e = tid + j * 256;
            cp_async16(dst + e * 16, src + e);
        }
        asm volatile("cp.async.commit_group;");
    };

    // exact rescore of one per-lane row's candidates; returns argmin (all lanes)
    auto rescore_row = [&](int row, const float v[4], const int id[4],
                           float m) -> int {
        float bestd = __int_as_float(0x7f800000);
        int   bestk = 0x7fffffff;
        if (v[0] <= m + DELTA) {
            const float4* xr = reinterpret_cast<const float4*>(X + (size_t)row * DDIM);
            float l0 = 0.f, l1 = 0.f, l2 = 0.f, l3 = 0.f;
            #pragma unroll
            for (int j = 0; j < 16; ++j) {
                float4 xv = xr[j];
                l0 = fmaf(xv.x, xv.x, l0);
                l1 = fmaf(xv.y, xv.y, l1);
                l2 = fmaf(xv.z, xv.z, l2);
                l3 = fmaf(xv.w, xv.w, l3);
            }
            float l2x = (l0 + l1) + (l2 + l3);
            #pragma unroll
            for (int j = 0; j < 4; ++j) {
                if (v[j] > m + DELTA) break;
                int k = id[j];
                float a0 = 0.f, a1 = 0.f, a2 = 0.f, a3 = 0.f;
                #pragma unroll
                for (int jj = 0; jj < 16; ++jj) {
                    float4 xv = xr[jj];
                    a0 = fmaf(xv.x, CB[(4 * jj + 0) * KCB + k], a0);
                    a1 = fmaf(xv.y, CB[(4 * jj + 1) * KCB + k], a1);
                    a2 = fmaf(xv.z, CB[(4 * jj + 2) * KCB + k], a2);
                    a3 = fmaf(xv.w, CB[(4 * jj + 3) * KCB + k], a3);
                }
                float dot = (a0 + a1) + (a2 + a3);
                float d = fmaf(-2.f, dot, l2x) + s_l2[k];
                if (d < bestd || (d == bestd && k < bestk)) { bestd = d; bestk = k; }
            }
        }
        #pragma unroll
        for (int off = 1; off < 4; off <<= 1) {
            float od = __shfl_xor_sync(0xffffffffu, bestd, off);
            int   ok = __shfl_xor_sync(0xffffffffu, bestk, off);
            if (od < bestd || (od == bestd && ok < bestk)) { bestd = od; bestk = ok; }
        }
        return bestk;
    };

    for (int chunk = blockIdx.x; chunk < NCHUNKS; chunk += GRID_A) {
        const int warp_base = chunk * ROWS_PER_CHUNK + wid * 32;

        // A fragments (hi only) for 2 m-tiles (32 rows)
        uint32_t Ah[2][8][4];
        #pragma unroll
        for (int m = 0; m < 2; ++m) {
            const int rA = warp_base + m * 16 + g;
            const int rB = rA + 8;
            #pragma unroll
            for (int ks = 0; ks < 8; ++ks) {
                Ah[m][ks][0] = tf32_hi(X[(size_t)rA * DDIM + ks * 8 + t]);
                Ah[m][ks][1] = tf32_hi(X[(size_t)rB * DDIM + ks * 8 + t]);
                Ah[m][ks][2] = tf32_hi(X[(size_t)rA * DDIM + ks * 8 + t + 4]);
                Ah[m][ks][3] = tf32_hi(X[(size_t)rB * DDIM + ks * 8 + t + 4]);
            }
        }

        __syncthreads();             // prev chunk's compute fully done
        stage(0);
        stage(1);

        const float INF = __int_as_float(0x7f800000);
        float v[4][4]; int id[4][4];
        #pragma unroll
        for (int rv = 0; rv < 4; ++rv) {
            v[rv][0] = v[rv][1] = v[rv][2] = v[rv][3] = INF;
            id[rv][0] = id[rv][1] = id[rv][2] = id[rv][3] = 0;
        }

        for (int tt = 0; tt < NTILES; ++tt) {
            if (tt == NTILES - 1) { asm volatile("cp.async.wait_group 0;"); }
            else                  { asm volatile("cp.async.wait_group 1;"); }
            __syncthreads();

            const float* sb = s_b + (tt % 3) * TILE_HI;

            #pragma unroll
            for (int nb = 0; nb < 8; ++nb) {
                float c0[4] = {0.f, 0.f, 0.f, 0.f};
                float c1[4] = {0.f, 0.f, 0.f, 0.f};

                #pragma unroll
                for (int ks = 0; ks < 8; ++ks) {
                    float2 bp = *reinterpret_cast<const float2*>(
                        &sb[(ks * 8 + nb) * 64 + lane * 2]);
                    uint32_t bx = __float_as_uint(bp.x);
                    uint32_t by = __float_as_uint(bp.y);
                    mma8(c0, Ah[0][ks], bx, by);
                    mma8(c1, Ah[1][ks], bx, by);
                }

                const int col = tt * KT + nb * 8 + 2 * t;
                float2 l2p = *reinterpret_cast<const float2*>(&s_l2[col]);
                top4_ins(fmaf(-2.f, c0[0], l2p.x), col,     v[0], id[0]);
                top4_ins(fmaf(-2.f, c0[1], l2p.y), col + 1, v[0], id[0]);
                top4_ins(fmaf(-2.f, c0[2], l2p.x), col,     v[1], id[1]);
                top4_ins(fmaf(-2.f, c0[3], l2p.y), col + 1, v[1], id[1]);
                top4_ins(fmaf(-2.f, c1[0], l2p.x), col,     v[2], id[2]);
                top4_ins(fmaf(-2.f, c1[1], l2p.y), col + 1, v[2], id[2]);
                top4_ins(fmaf(-2.f, c1[2], l2p.x), col,     v[3], id[3]);
                top4_ins(fmaf(-2.f, c1[3], l2p.y), col + 1, v[3], id[3]);
            }

            if (tt + 2 < NTILES) stage(tt + 2);   // writes buf computed at tt-1
        }

        // approx min per row-var over the quad, then exact rescore
        int bi[4];
        #pragma unroll
        for (int rv = 0; rv < 4; ++rv) {
            float m = v[rv][0];
            #pragma unroll
            for (int off = 1; off < 4; off <<= 1)
                m = fminf(m, __shfl_xor_sync(0xffffffffu, m, off));
            const int row = warp_base + (rv >> 1) * 16 + (rv & 1) * 8 + g;
            bi[rv] = rescore_row(row, v[rv], id[rv], m);
        }

        if (t == 0) {
            #pragma unroll
            for (int rv = 0; rv < 4; ++rv) {
                const int row = warp_base + (rv >> 1) * 16 + (rv & 1) * 8 + g;
                g_idx[row] = bi[rv];
                atomicAdd(&g_counts[bi[rv]], 1.0f);
            }
        }

        // scatter input sums: 32 rows x 64 dims per warp
        #pragma unroll
        for (int r = 0; r < 32; ++r) {
            const int rv = r >> 3;
            int idx = __shfl_sync(0xffffffffu, bi[rv], (r & 7) * 4);
            const int row = warp_base + (rv >> 1) * 16 + (rv & 1) * 8 + (r & 7);
            float va = X[(size_t)row * DDIM + lane];
            float vb = X[(size_t)row * DDIM + lane + 32];
            atomicAdd(&g_isum[idx * DDIM + lane], va);
            atomicAdd(&g_isum[idx * DDIM + lane + 32], vb);
        }
    }
}

// ---------------------------------------------------------------------------
// Kernel B1: EMA cluster sizes + total + inverse cluster size (1 block)
// ---------------------------------------------------------------------------
__global__ __launch_bounds__(1024) void k_ema_a(
        const float* __restrict__ ema_cs, float* __restrict__ out)
{
    __shared__ float red[1024];
    const int k = threadIdx.x;

    float ne = DECAY * ema_cs[k] + ONEMD * g_counts[k];
    out[OFF_ECS + k] = ne;

    red[k] = ne;
    __syncthreads();
    for (int s = 512; s > 0; s >>= 1) {
        if (k < s) red[k] += red[k + s];
        __syncthreads();
    }
    const float n = red[0];
    const float norm = (ne + EPS) / (n + (float)KCB * EPS);
    g_invcs[k] = 1.0f / (norm * n);
}

// ---------------------------------------------------------------------------
// Kernel B2: elementwise EMA input-sum + new codebook (chip-wide)
// ---------------------------------------------------------------------------
__global__ __launch_bounds__(256) void k_ema_b(
        const float* __restrict__ ema_eis, float* __restrict__ out)
{
    int i = blockIdx.x * blockDim.x + threadIdx.x;   // 0..65535
    int k = i & (KCB - 1);
    int d = i >> 10;
    float eis = DECAY * ema_eis[d * KCB + k] + ONEMD * g_isum[k * DDIM + d];
    out[OFF_EIS + d * KCB + k] = eis;
    float nc = eis * g_invcs[k];
    out[OFF_NCB + d * KCB + k] = nc;
    g_ncbT[k * DDIM + d] = nc;
}

// ---------------------------------------------------------------------------
// Kernel C: gather + straight-through + loss (float4)
// ---------------------------------------------------------------------------
__global__ __launch_bounds__(256) void k_gather_loss(
        const float* __restrict__ X, float* __restrict__ out)
{
    float acc = 0.0f;
    const int total4 = N_ROWS * DDIM / 4;
    const float4* X4 = reinterpret_cast<const float4*>(X);
    const float4* Q4 = reinterpret_cast<const float4*>(g_ncbT);
    float4* O4 = reinterpret_cast<float4*>(out + OFF_Q);

    for (int e = blockIdx.x * blockDim.x + threadIdx.x; e < total4;
         e += gridDim.x * blockDim.x) {
        int n  = e >> 4;
        int d4 = e & 15;
        float4 q = Q4[(g_idx[n] << 4) | d4];
        float4 x = X4[e];
        float dx = q.x - x.x, dy = q.y - x.y, dz = q.z - x.z, dw = q.w - x.w;
        float4 o;
        o.x = x.x + dx; o.y = x.y + dy; o.z = x.z + dz; o.w = x.w + dw;
        O4[e] = o;
        acc = fmaf(dx, dx, acc);
        acc = fmaf(dy, dy, acc);
        acc = fmaf(dz, dz, acc);
        acc = fmaf(dw, dw, acc);
    }
    #pragma unroll
    for (int o = 16; o > 0; o >>= 1)
        acc += __shfl_down_sync(0xffffffffu, acc, o);
    __shared__ float warpsum[8];
    int lane = threadIdx.x & 31, wid = threadIdx.x >> 5;
    if (lane == 0) warpsum[wid] = acc;
    __syncthreads();
    if (wid == 0) {
        float vv = (lane < 8) ? warpsum[lane] : 0.0f;
        #pragma unroll
        for (int o = 4; o > 0; o >>= 1)
            vv += __shfl_down_sync(0xffffffffu, vv, o);
        if (lane == 0) atomicAdd(g_loss, vv);
    }
}

__global__ void k_loss_finalize(float* __restrict__ out) {
    out[OFF_LOSS] = g_loss[0] * (1.0f / (float)(N_ROWS * DDIM));
}

// ---------------------------------------------------------------------------
extern "C" void kernel_launch(void* const* d_in, const int* in_sizes, int n_in,
                              void* d_out, int out_size) {
    const float* X       = (const float*)d_in[0];
    const float* CB      = (const float*)d_in[1];
    const float* EMA_CS  = (const float*)d_in[2];
    const float* EMA_EIS = (const float*)d_in[3];
    float* out = (float*)d_out;

    static const size_t dyn_smem = (KCB + 3 * TILE_HI) * sizeof(float); // 53248
    cudaFuncSetAttribute(k_argmin_scatter,
                         cudaFuncAttributeMaxDynamicSharedMemorySize,
                         (int)dyn_smem);

    k_init<<<256, 256>>>(CB);
    k_argmin_scatter<<<GRID_A, 256, dyn_smem>>>(X, CB);
    k_ema_a<<<1, 1024>>>(EMA_CS, out);
    k_ema_b<<<256, 256>>>(EMA_EIS, out);
    k_gather_loss<<<2048, 256>>>(X, out);
    k_loss_finalize<<<1, 1>>>(out);
}

// round 5
// speedup vs baseline: 1.5275x; 1.0518x over previous
#include <cuda_runtime.h>
#include <cuda_bf16.h>
#include <cstdint>

// Problem constants
#define N_ROWS   131072
#define DDIM     64
#define KCB      1024
#define DECAY    0.99f
#define ONEMD    0.01f
#define EPS      1e-5f
#define DELTA    0.6f        // rescore margin (covers bf16 approx error)

#define NGROUPS  (N_ROWS / 32)   // 4096 warp work units (32 rows each)
#define GRID_A   148

// Output layout
#define OFF_Q    0
#define OFF_LOSS (N_ROWS*DDIM)
#define OFF_NCB  (OFF_LOSS + 1)
#define OFF_ECS  (OFF_NCB + DDIM*KCB)
#define OFF_EIS  (OFF_ECS + KCB)

// Scratch
__device__ int            g_idx[N_ROWS];
__device__ float          g_counts[KCB];
__device__ float          g_isum[KCB * DDIM];     // [k][d]
__device__ float          g_l2cb[KCB];
__device__ float          g_invcs[KCB];
__device__ float          g_ncbT[KCB * DDIM];     // [k][d]
__device__ float          g_loss[1];
__device__ int            g_work;
__device__ __nv_bfloat16  g_cbbf[KCB * DDIM];     // fragment-major bf16 image (128KB)

// ---------------------------------------------------------------------------
__device__ __forceinline__ uint32_t packbf(float lo, float hi) {
    __nv_bfloat162 h = __floats2bfloat162_rn(lo, hi);
    return *reinterpret_cast<uint32_t*>(&h);
}

__device__ __forceinline__ void mma16(float c[4], const uint32_t a[4],
                                      uint32_t b0, uint32_t b1) {
    asm volatile(
        "mma.sync.aligned.m16n8k16.row.col.f32.bf16.bf16.f32 "
        "{%0,%1,%2,%3},{%4,%5,%6,%7},{%8,%9},{%0,%1,%2,%3};"
        : "+f"(c[0]), "+f"(c[1]), "+f"(c[2]), "+f"(c[3])
        : "r"(a[0]), "r"(a[1]), "r"(a[2]), "r"(a[3]), "r"(b0), "r"(b1));
}

__device__ __forceinline__ void cp_async16(uint32_t smem_dst, const void* gsrc) {
    asm volatile("cp.async.cg.shared.global [%0], [%1], 16;"
                 :: "r"(smem_dst), "l"(gsrc));
}

// sorted top-4 insertion (ascending)
__device__ __forceinline__ void top4_ins(float s, int k, float v[4], int id[4]) {
    if (s < v[3]) {
        if (s < v[1]) {
            v[3] = v[2]; id[3] = id[2];
            v[2] = v[1]; id[2] = id[1];
            if (s < v[0]) { v[1] = v[0]; id[1] = id[0]; v[0] = s; id[0] = k; }
            else          { v[1] = s; id[1] = k; }
        } else {
            if (s < v[2]) { v[3] = v[2]; id[3] = id[2]; v[2] = s; id[2] = k; }
            else          { v[3] = s; id[3] = k; }
        }
    }
}

// ---------------------------------------------------------------------------
// Kernel 0: zero g_isum + build fragment-major bf16 codebook image.
// Fragment (tt, ks16, nb): 64 u32 (32 lanes x 2 regs); value (k=dk, n) at
// lane = g*4+t (g = n%8 within nb, t = (dk>>1)&3), reg = dk>>3, half = dk&1.
// ---------------------------------------------------------------------------
__global__ void k_init_image(const float* __restrict__ cb) {
    int i = blockIdx.x * blockDim.x + threadIdx.x;   // 0..65535
    int n = i & (KCB - 1);
    int d = i >> 10;

    g_isum[i] = 0.0f;

    float x = cb[d * KCB + n];
    int tt = n >> 6, nl = n & 63;
    int nb = nl >> 3, g = nl & 7;
    int ks = d >> 4, dk = d & 15;
    int t = (dk >> 1) & 3, reg = dk >> 3, half = dk & 1;
    int lane = g * 4 + t;
    int u32idx = ((tt * 32) + ks * 8 + nb) * 64 + lane * 2 + reg;
    g_cbbf[u32idx * 2 + half] = __float2bfloat16_rn(x);
}

// Kernel 1: ||c_k||^2 (grid 16 x 256; block b handles 64 codewords)
__global__ void k_l2cb(const float* __restrict__ cb) {
    __shared__ float part[256];
    int nl = threadIdx.x & 63, dq = threadIdx.x >> 6;
    int n = blockIdx.x * 64 + nl;
    float s = 0.0f;
    #pragma unroll
    for (int j = 0; j < 16; ++j) {
        float c = cb[(dq * 16 + j) * KCB + n];
        s = fmaf(c, c, s);
    }
    part[threadIdx.x] = s;
    __syncthreads();
    if (dq == 0)
        g_l2cb[n] = (part[nl] + part[64 + nl]) + (part[128 + nl] + part[192 + nl]);
}

// Kernel 2: small zeroing (counts, loss, work counter)
__global__ void k_zero_small() {
    int i = threadIdx.x;
    g_counts[i] = 0.0f;
    if (i == 0) { g_loss[0] = 0.0f; g_work = 0; }
}

// ---------------------------------------------------------------------------
// Kernel A: bf16 tensor argmin + exact fp32 rescore + scatter.
// 512 threads, whole bf16 codebook resident in smem, no mainloop barriers,
// atomic work queue of 32-row groups.
// ---------------------------------------------------------------------------
extern __shared__ float s_dyn[];

__global__ __launch_bounds__(512, 1) void k_argmin_scatter(
        const float* __restrict__ X, const float* __restrict__ CB)
{
    float*    s_l2 = s_dyn;                                    // 1024 floats
    uint32_t* s_cb = reinterpret_cast<uint32_t*>(s_dyn + KCB); // 32768 u32

    const int tid  = threadIdx.x;
    const int lane = tid & 31;
    const int g    = lane >> 2;
    const int t    = lane & 3;

    for (int i = tid; i < KCB; i += 512) s_l2[i] = g_l2cb[i];

    // load bf16 codebook image (128 KB) once
    {
        const uint32_t sb = (uint32_t)__cvta_generic_to_shared(s_cb);
        const float4* src = reinterpret_cast<const float4*>(g_cbbf);
        #pragma unroll
        for (int j = 0; j < 16; ++j) {
            int e = tid + j * 512;
            cp_async16(sb + e * 16, src + e);
        }
        asm volatile("cp.async.commit_group;");
        asm volatile("cp.async.wait_group 0;");
    }
    __syncthreads();

    // exact rescore (per-lane candidates; returns argmin to all lanes of quad)
    auto rescore_row = [&](int row, const float v[4], const int id[4],
                           float m) -> int {
        float bestd = __int_as_float(0x7f800000);
        int   bestk = 0x7fffffff;
        if (v[0] <= m + DELTA) {
            const float4* xr = reinterpret_cast<const float4*>(X + (size_t)row * DDIM);
            float l0 = 0.f, l1 = 0.f, l2 = 0.f, l3 = 0.f;
            #pragma unroll
            for (int j = 0; j < 16; ++j) {
                float4 xv = xr[j];
                l0 = fmaf(xv.x, xv.x, l0);
                l1 = fmaf(xv.y, xv.y, l1);
                l2 = fmaf(xv.z, xv.z, l2);
                l3 = fmaf(xv.w, xv.w, l3);
            }
            float l2x = (l0 + l1) + (l2 + l3);
            #pragma unroll
            for (int j = 0; j < 4; ++j) {
                if (v[j] > m + DELTA) break;
                int k = id[j];
                float a0 = 0.f, a1 = 0.f, a2 = 0.f, a3 = 0.f;
                #pragma unroll
                for (int jj = 0; jj < 16; ++jj) {
                    float4 xv = xr[jj];
                    a0 = fmaf(xv.x, CB[(4 * jj + 0) * KCB + k], a0);
                    a1 = fmaf(xv.y, CB[(4 * jj + 1) * KCB + k], a1);
                    a2 = fmaf(xv.z, CB[(4 * jj + 2) * KCB + k], a2);
                    a3 = fmaf(xv.w, CB[(4 * jj + 3) * KCB + k], a3);
                }
                float dot = (a0 + a1) + (a2 + a3);
                float d = fmaf(-2.f, dot, l2x) + s_l2[k];
                if (d < bestd || (d == bestd && k < bestk)) { bestd = d; bestk = k; }
            }
        }
        #pragma unroll
        for (int off = 1; off < 4; off <<= 1) {
            float od = __shfl_xor_sync(0xffffffffu, bestd, off);
            int   ok = __shfl_xor_sync(0xffffffffu, bestk, off);
            if (od < bestd || (od == bestd && ok < bestk)) { bestd = od; bestk = ok; }
        }
        return bestk;
    };

    for (;;) {
        int gid = 0;
        if (lane == 0) gid = atomicAdd(&g_work, 1);
        gid = __shfl_sync(0xffffffffu, gid, 0);
        if (gid >= NGROUPS) break;

        const int base = gid * 32;

        // A fragments (bf16) for 2 m-tiles (32 rows)
        uint32_t Ah[2][4][4];
        #pragma unroll
        for (int m = 0; m < 2; ++m) {
            const int rA = base + m * 16 + g;
            const float* xa = X + (size_t)rA * DDIM;
            const float* xb = xa + 8 * DDIM;
            #pragma unroll
            for (int ks = 0; ks < 4; ++ks) {
                int c0i = ks * 16 + 2 * t;
                Ah[m][ks][0] = packbf(xa[c0i],     xa[c0i + 1]);
                Ah[m][ks][1] = packbf(xb[c0i],     xb[c0i + 1]);
                Ah[m][ks][2] = packbf(xa[c0i + 8], xa[c0i + 9]);
                Ah[m][ks][3] = packbf(xb[c0i + 8], xb[c0i + 9]);
            }
        }

        const float INF = __int_as_float(0x7f800000);
        float v[4][4]; int id[4][4];
        #pragma unroll
        for (int rv = 0; rv < 4; ++rv) {
            v[rv][0] = v[rv][1] = v[rv][2] = v[rv][3] = INF;
            id[rv][0] = id[rv][1] = id[rv][2] = id[rv][3] = 0;
        }

        #pragma unroll 2
        for (int tt = 0; tt < 16; ++tt) {
            #pragma unroll
            for (int nb = 0; nb < 8; ++nb) {
                float c0[4] = {0.f, 0.f, 0.f, 0.f};
                float c1[4] = {0.f, 0.f, 0.f, 0.f};
                #pragma unroll
                for (int ks = 0; ks < 4; ++ks) {
                    uint2 bp = *reinterpret_cast<const uint2*>(
                        &s_cb[((tt * 32) + ks * 8 + nb) * 64 + lane * 2]);
                    mma16(c0, Ah[0][ks], bp.x, bp.y);
                    mma16(c1, Ah[1][ks], bp.x, bp.y);
                }
                const int col = tt * 64 + nb * 8 + 2 * t;
                float2 l2p = *reinterpret_cast<const float2*>(&s_l2[col]);
                top4_ins(fmaf(-2.f, c0[0], l2p.x), col,     v[0], id[0]);
                top4_ins(fmaf(-2.f, c0[1], l2p.y), col + 1, v[0], id[0]);
                top4_ins(fmaf(-2.f, c0[2], l2p.x), col,     v[1], id[1]);
                top4_ins(fmaf(-2.f, c0[3], l2p.y), col + 1, v[1], id[1]);
                top4_ins(fmaf(-2.f, c1[0], l2p.x), col,     v[2], id[2]);
                top4_ins(fmaf(-2.f, c1[1], l2p.y), col + 1, v[2], id[2]);
                top4_ins(fmaf(-2.f, c1[2], l2p.x), col,     v[3], id[3]);
                top4_ins(fmaf(-2.f, c1[3], l2p.y), col + 1, v[3], id[3]);
            }
        }

        // per-row approx min over the quad, exact rescore
        int bi[4];
        #pragma unroll
        for (int rv = 0; rv < 4; ++rv) {
            float m = v[rv][0];
            #pragma unroll
            for (int off = 1; off < 4; off <<= 1)
                m = fminf(m, __shfl_xor_sync(0xffffffffu, m, off));
            const int row = base + (rv >> 1) * 16 + (rv & 1) * 8 + g;
            bi[rv] = rescore_row(row, v[rv], id[rv], m);
        }

        if (t == 0) {
            #pragma unroll
            for (int rv = 0; rv < 4; ++rv) {
                const int row = base + (rv >> 1) * 16 + (rv & 1) * 8 + g;
                g_idx[row] = bi[rv];
                atomicAdd(&g_counts[bi[rv]], 1.0f);
            }
        }

        // scatter input sums: 32 rows x 64 dims
        #pragma unroll
        for (int r = 0; r < 32; ++r) {
            const int rv = r >> 3;
            int idx = __shfl_sync(0xffffffffu, bi[rv], (r & 7) * 4);
            const int row = base + (rv >> 1) * 16 + (rv & 1) * 8 + (r & 7);
            float va = X[(size_t)row * DDIM + lane];
            float vb = X[(size_t)row * DDIM + lane + 32];
            atomicAdd(&g_isum[idx * DDIM + lane], va);
            atomicAdd(&g_isum[idx * DDIM + lane + 32], vb);
        }
    }
}

// ---------------------------------------------------------------------------
// Kernel B1: EMA cluster sizes + inverse cluster size (1 block)
// ---------------------------------------------------------------------------
__global__ __launch_bounds__(1024) void k_ema_a(
        const float* __restrict__ ema_cs, float* __restrict__ out)
{
    __shared__ float red[1024];
    const int k = threadIdx.x;

    float ne = DECAY * ema_cs[k] + ONEMD * g_counts[k];
    out[OFF_ECS + k] = ne;

    red[k] = ne;
    __syncthreads();
    for (int s = 512; s > 0; s >>= 1) {
        if (k < s) red[k] += red[k + s];
        __syncthreads();
    }
    const float n = red[0];
    const float norm = (ne + EPS) / (n + (float)KCB * EPS);
    g_invcs[k] = 1.0f / (norm * n);
}

// Kernel B2: EMA input-sum + new codebook (elementwise)
__global__ __launch_bounds__(256) void k_ema_b(
        const float* __restrict__ ema_eis, float* __restrict__ out)
{
    int i = blockIdx.x * blockDim.x + threadIdx.x;
    int k = i & (KCB - 1);
    int d = i >> 10;
    float eis = DECAY * ema_eis[d * KCB + k] + ONEMD * g_isum[k * DDIM + d];
    out[OFF_EIS + d * KCB + k] = eis;
    float nc = eis * g_invcs[k];
    out[OFF_NCB + d * KCB + k] = nc;
    g_ncbT[k * DDIM + d] = nc;
}

// ---------------------------------------------------------------------------
// Kernel C: gather + straight-through + loss (float4, 2-way MLP)
// grid 4096 x 256 -> 1,048,576 threads; 2,097,152 float4 elements.
// ---------------------------------------------------------------------------
__global__ __launch_bounds__(256) void k_gather_loss(
        const float* __restrict__ X, float* __restrict__ out)
{
    const int H = (N_ROWS * DDIM / 4) / 2;   // 1048576
    const int e0 = blockIdx.x * blockDim.x + threadIdx.x;
    const int e1 = e0 + H;
    const float4* X4 = reinterpret_cast<const float4*>(X);
    const float4* Q4 = reinterpret_cast<const float4*>(g_ncbT);
    float4* O4 = reinterpret_cast<float4*>(out + OFF_Q);

    int n0 = e0 >> 4, n1 = e1 >> 4;
    int i0 = g_idx[n0], i1 = g_idx[n1];
    float4 x0 = X4[e0], x1 = X4[e1];
    float4 q0 = Q4[(i0 << 4) | (e0 & 15)];
    float4 q1 = Q4[(i1 << 4) | (e1 & 15)];

    float acc = 0.0f;
    float dx, dy, dz, dw;
    float4 o;
    dx = q0.x - x0.x; dy = q0.y - x0.y; dz = q0.z - x0.z; dw = q0.w - x0.w;
    o.x = x0.x + dx; o.y = x0.y + dy; o.z = x0.z + dz; o.w = x0.w + dw;
    O4[e0] = o;
    acc = fmaf(dx, dx, acc); acc = fmaf(dy, dy, acc);
    acc = fmaf(dz, dz, acc); acc = fmaf(dw, dw, acc);
    dx = q1.x - x1.x; dy = q1.y - x1.y; dz = q1.z - x1.z; dw = q1.w - x1.w;
    o.x = x1.x + dx; o.y = x1.y + dy; o.z = x1.z + dz; o.w = x1.w + dw;
    O4[e1] = o;
    acc = fmaf(dx, dx, acc); acc = fmaf(dy, dy, acc);
    acc = fmaf(dz, dz, acc); acc = fmaf(dw, dw, acc);

    #pragma unroll
    for (int o2 = 16; o2 > 0; o2 >>= 1)
        acc += __shfl_down_sync(0xffffffffu, acc, o2);
    __shared__ float warpsum[8];
    int lane = threadIdx.x & 31, wid = threadIdx.x >> 5;
    if (lane == 0) warpsum[wid] = acc;
    __syncthreads();
    if (wid == 0) {
        float vv = (lane < 8) ? warpsum[lane] : 0.0f;
        #pragma unroll
        for (int o2 = 4; o2 > 0; o2 >>= 1)
            vv += __shfl_down_sync(0xffffffffu, vv, o2);
        if (lane == 0) atomicAdd(g_loss, vv);
    }
}

__global__ void k_loss_finalize(float* __restrict__ out) {
    out[OFF_LOSS] = g_loss[0] * (1.0f / (float)(N_ROWS * DDIM));
}

// ---------------------------------------------------------------------------
extern "C" void kernel_launch(void* const* d_in, const int* in_sizes, int n_in,
                              void* d_out, int out_size) {
    const float* X       = (const float*)d_in[0];
    const float* CB      = (const float*)d_in[1];
    const float* EMA_CS  = (const float*)d_in[2];
    const float* EMA_EIS = (const float*)d_in[3];
    float* out = (float*)d_out;

    static const size_t dyn_smem = KCB * 4 + KCB * DDIM * 2;   // 4KB + 128KB
    cudaFuncSetAttribute(k_argmin_scatter,
                         cudaFuncAttributeMaxDynamicSharedMemorySize,
                         (int)dyn_smem);

    k_init_image<<<256, 256>>>(CB);                 // launch 0
    k_l2cb<<<16, 256>>>(CB);                        // launch 1
    k_zero_small<<<1, 1024>>>();                    // launch 2
    k_argmin_scatter<<<GRID_A, 512, dyn_smem>>>(X, CB);  // launch 3 (profiled)
    k_ema_a<<<1, 1024>>>(EMA_CS, out);              // launch 4
    k_ema_b<<<256, 256>>>(EMA_EIS, out);            // launch 5
    k_gather_loss<<<4096, 256>>>(X, out);           // launch 6
    k_loss_finalize<<<1, 1>>>(out);                 // launch 7
}

// round 6
// speedup vs baseline: 1.6769x; 1.0978x over previous
#include <cuda_runtime.h>
#include <cuda_bf16.h>
#include <cstdint>

// Problem constants
#define N_ROWS   131072
#define DDIM     64
#define KCB      1024
#define DECAY    0.99f
#define ONEMD    0.01f
#define EPS      1e-5f
#define DELTA    0.6f        // window margin (>= 2x worst-case bf16 approx error)

#define NGROUPS  (N_ROWS / 32)   // 4096 warp work units
#define GRID_A   148

// Output layout
#define OFF_Q    0
#define OFF_LOSS (N_ROWS*DDIM)
#define OFF_NCB  (OFF_LOSS + 1)
#define OFF_ECS  (OFF_NCB + DDIM*KCB)
#define OFF_EIS  (OFF_ECS + KCB)

// Scratch
__device__ int            g_idx[N_ROWS];
__device__ float          g_counts[KCB];
__device__ float          g_isum[KCB * DDIM];     // [k][d]
__device__ float          g_l2cb[KCB];
__device__ float          g_invcs[KCB];
__device__ float          g_ncbT[KCB * DDIM];     // [k][d]
__device__ float          g_loss[1];
__device__ int            g_work;
__device__ __nv_bfloat16  g_cbbf[KCB * DDIM];     // fragment-major bf16 image (128KB)

// ---------------------------------------------------------------------------
__device__ __forceinline__ uint32_t packbf(float lo, float hi) {
    __nv_bfloat162 h = __floats2bfloat162_rn(lo, hi);
    return *reinterpret_cast<uint32_t*>(&h);
}

__device__ __forceinline__ void mma16(float c[4], const uint32_t a[4],
                                      uint32_t b0, uint32_t b1) {
    asm volatile(
        "mma.sync.aligned.m16n8k16.row.col.f32.bf16.bf16.f32 "
        "{%0,%1,%2,%3},{%4,%5,%6,%7},{%8,%9},{%0,%1,%2,%3};"
        : "+f"(c[0]), "+f"(c[1]), "+f"(c[2]), "+f"(c[3])
        : "r"(a[0]), "r"(a[1]), "r"(a[2]), "r"(a[3]), "r"(b0), "r"(b1));
}

__device__ __forceinline__ void cp_async16(uint32_t smem_dst, const void* gsrc) {
    asm volatile("cp.async.cg.shared.global [%0], [%1], 16;"
                 :: "r"(smem_dst), "l"(gsrc));
}

// exact reduced score (l2cb - 2*dot), fp32, 4 accumulators
__device__ __forceinline__ float exact_sc(const float* __restrict__ X,
                                          const float* __restrict__ CB,
                                          const float* __restrict__ s_l2,
                                          int row, int k) {
    const float4* xr = reinterpret_cast<const float4*>(X + (size_t)row * DDIM);
    float a0 = 0.f, a1 = 0.f, a2 = 0.f, a3 = 0.f;
    #pragma unroll
    for (int jj = 0; jj < 16; ++jj) {
        float4 xv = xr[jj];
        a0 = fmaf(xv.x, CB[(4 * jj + 0) * KCB + k], a0);
        a1 = fmaf(xv.y, CB[(4 * jj + 1) * KCB + k], a1);
        a2 = fmaf(xv.z, CB[(4 * jj + 2) * KCB + k], a2);
        a3 = fmaf(xv.w, CB[(4 * jj + 3) * KCB + k], a3);
    }
    return fmaf(-2.f, (a0 + a1) + (a2 + a3), s_l2[k]);
}

// ---------------------------------------------------------------------------
// Kernel 0: zero g_isum + build fragment-major bf16 codebook image
// ---------------------------------------------------------------------------
__global__ void k_init_image(const float* __restrict__ cb) {
    int i = blockIdx.x * blockDim.x + threadIdx.x;   // 0..65535
    int n = i & (KCB - 1);
    int d = i >> 10;

    g_isum[i] = 0.0f;

    float x = cb[d * KCB + n];
    int tt = n >> 6, nl = n & 63;
    int nb = nl >> 3, g = nl & 7;
    int ks = d >> 4, dk = d & 15;
    int t = (dk >> 1) & 3, reg = dk >> 3, half = dk & 1;
    int lane = g * 4 + t;
    int u32idx = ((tt * 32) + ks * 8 + nb) * 64 + lane * 2 + reg;
    g_cbbf[u32idx * 2 + half] = __float2bfloat16_rn(x);
}

// Kernel 1: ||c_k||^2 + small zeroing
__global__ void k_l2cb(const float* __restrict__ cb) {
    __shared__ float part[256];
    int nl = threadIdx.x & 63, dq = threadIdx.x >> 6;
    int n = blockIdx.x * 64 + nl;
    float s = 0.0f;
    #pragma unroll
    for (int j = 0; j < 16; ++j) {
        float c = cb[(dq * 16 + j) * KCB + n];
        s = fmaf(c, c, s);
    }
    part[threadIdx.x] = s;
    __syncthreads();
    if (dq == 0)
        g_l2cb[n] = (part[nl] + part[64 + nl]) + (part[128 + nl] + part[192 + nl]);
    if (blockIdx.x == 0) {
        int i = threadIdx.x;
        if (i < 256) { g_counts[i] = 0.f; g_counts[i+256] = 0.f;
                       g_counts[i+512] = 0.f; g_counts[i+768] = 0.f; }
        if (i == 0) { g_loss[0] = 0.0f; g_work = 0; }
    }
}

// ---------------------------------------------------------------------------
// Kernel A: two-pass bf16 tensor argmin + exact rescore + scatter.
// Pass1: MMA + min-only epilogue. Pass2: MMA + threshold collect (rare).
// ---------------------------------------------------------------------------
extern __shared__ float s_dyn[];

#define INS(RV, S, COL) do { if ((S) < th[RV]) {          \
      if      (cnt[RV] == 0) cand[RV][0] = (COL);          \
      else if (cnt[RV] == 1) cand[RV][1] = (COL);          \
      else if (cnt[RV] == 2) cand[RV][2] = (COL);          \
      else if (cnt[RV] == 3) cand[RV][3] = (COL);          \
      cnt[RV]++; } } while (0)

__global__ __launch_bounds__(512, 1) void k_argmin_scatter(
        const float* __restrict__ X, const float* __restrict__ CB)
{
    float*    s_l2 = s_dyn;                                    // 1024 floats
    uint32_t* s_cb = reinterpret_cast<uint32_t*>(s_dyn + KCB); // 32768 u32

    const int tid  = threadIdx.x;
    const int lane = tid & 31;
    const int g    = lane >> 2;
    const int t    = lane & 3;

    for (int i = tid; i < KCB; i += 512) s_l2[i] = g_l2cb[i];
    {
        const uint32_t sb = (uint32_t)__cvta_generic_to_shared(s_cb);
        const float4* src = reinterpret_cast<const float4*>(g_cbbf);
        #pragma unroll
        for (int j = 0; j < 16; ++j) {
            int e = tid + j * 512;
            cp_async16(sb + e * 16, src + e);
        }
        asm volatile("cp.async.commit_group;");
        asm volatile("cp.async.wait_group 0;");
    }
    __syncthreads();

    const float INF = __int_as_float(0x7f800000);

    for (;;) {
        int gid = 0;
        if (lane == 0) gid = atomicAdd(&g_work, 1);
        gid = __shfl_sync(0xffffffffu, gid, 0);
        if (gid >= NGROUPS) break;

        const int base = gid * 32;

        // A fragments (bf16), 2 m-tiles = 32 rows
        uint32_t Ah[2][4][4];
        #pragma unroll
        for (int m = 0; m < 2; ++m) {
            const float* xa = X + (size_t)(base + m * 16 + g) * DDIM;
            const float* xb = xa + 8 * DDIM;
            #pragma unroll
            for (int ks = 0; ks < 4; ++ks) {
                int ci = ks * 16 + 2 * t;
                Ah[m][ks][0] = packbf(xa[ci],     xa[ci + 1]);
                Ah[m][ks][1] = packbf(xb[ci],     xb[ci + 1]);
                Ah[m][ks][2] = packbf(xa[ci + 8], xa[ci + 9]);
                Ah[m][ks][3] = packbf(xb[ci + 8], xb[ci + 9]);
            }
        }

        // ---------------- pass 1: min only ----------------
        float mn[4] = {INF, INF, INF, INF};
        #pragma unroll 2
        for (int tt = 0; tt < 16; ++tt) {
            #pragma unroll
            for (int nb = 0; nb < 8; ++nb) {
                float c0[4] = {0.f, 0.f, 0.f, 0.f};
                float c1[4] = {0.f, 0.f, 0.f, 0.f};
                #pragma unroll
                for (int ks = 0; ks < 4; ++ks) {
                    uint2 bp = *reinterpret_cast<const uint2*>(
                        &s_cb[((tt * 32) + ks * 8 + nb) * 64 + lane * 2]);
                    mma16(c0, Ah[0][ks], bp.x, bp.y);
                    mma16(c1, Ah[1][ks], bp.x, bp.y);
                }
                float2 l2p = *reinterpret_cast<const float2*>(
                    &s_l2[tt * 64 + nb * 8 + 2 * t]);
                mn[0] = fminf(mn[0], fmaf(-2.f, c0[0], l2p.x));
                mn[0] = fminf(mn[0], fmaf(-2.f, c0[1], l2p.y));
                mn[1] = fminf(mn[1], fmaf(-2.f, c0[2], l2p.x));
                mn[1] = fminf(mn[1], fmaf(-2.f, c0[3], l2p.y));
                mn[2] = fminf(mn[2], fmaf(-2.f, c1[0], l2p.x));
                mn[2] = fminf(mn[2], fmaf(-2.f, c1[1], l2p.y));
                mn[3] = fminf(mn[3], fmaf(-2.f, c1[2], l2p.x));
                mn[3] = fminf(mn[3], fmaf(-2.f, c1[3], l2p.y));
            }
        }

        float th[4];
        #pragma unroll
        for (int rv = 0; rv < 4; ++rv) {
            float m = mn[rv];
            m = fminf(m, __shfl_xor_sync(0xffffffffu, m, 1));
            m = fminf(m, __shfl_xor_sync(0xffffffffu, m, 2));
            th[rv] = m + DELTA;
        }

        // ---------------- pass 2: collect candidates ----------------
        int cnt[4] = {0, 0, 0, 0};
        int cand[4][4];
        #pragma unroll
        for (int rv = 0; rv < 4; ++rv) {
            cand[rv][0] = cand[rv][1] = cand[rv][2] = cand[rv][3] = 0;
        }

        #pragma unroll 2
        for (int tt = 0; tt < 16; ++tt) {
            #pragma unroll
            for (int nb = 0; nb < 8; ++nb) {
                float c0[4] = {0.f, 0.f, 0.f, 0.f};
                float c1[4] = {0.f, 0.f, 0.f, 0.f};
                #pragma unroll
                for (int ks = 0; ks < 4; ++ks) {
                    uint2 bp = *reinterpret_cast<const uint2*>(
                        &s_cb[((tt * 32) + ks * 8 + nb) * 64 + lane * 2]);
                    mma16(c0, Ah[0][ks], bp.x, bp.y);
                    mma16(c1, Ah[1][ks], bp.x, bp.y);
                }
                const int colb = tt * 64 + nb * 8 + 2 * t;
                float2 l2p = *reinterpret_cast<const float2*>(&s_l2[colb]);
                float s0 = fmaf(-2.f, c0[0], l2p.x);
                float s1 = fmaf(-2.f, c0[1], l2p.y);
                float s2 = fmaf(-2.f, c0[2], l2p.x);
                float s3 = fmaf(-2.f, c0[3], l2p.y);
                float s4 = fmaf(-2.f, c1[0], l2p.x);
                float s5 = fmaf(-2.f, c1[1], l2p.y);
                float s6 = fmaf(-2.f, c1[2], l2p.x);
                float s7 = fmaf(-2.f, c1[3], l2p.y);
                INS(0, s0, colb); INS(0, s1, colb + 1);
                INS(1, s2, colb); INS(1, s3, colb + 1);
                INS(2, s4, colb); INS(2, s5, colb + 1);
                INS(3, s6, colb); INS(3, s7, colb + 1);
            }
        }

        // ---------------- exact rescore of candidates ----------------
        int bi[4];
        #pragma unroll
        for (int rv = 0; rv < 4; ++rv) {
            const int row = base + (rv >> 1) * 16 + (rv & 1) * 8 + g;
            float bd = INF;
            int   bk = 0x7fffffff;
            #pragma unroll
            for (int sl = 0; sl < 4; ++sl) {
                if (sl < cnt[rv]) {
                    int k = cand[rv][sl];
                    float d = exact_sc(X, CB, s_l2, row, k);
                    if (d < bd || (d == bd && k < bk)) { bd = d; bk = k; }
                }
            }
            #pragma unroll
            for (int off = 1; off < 4; off <<= 1) {
                float od = __shfl_xor_sync(0xffffffffu, bd, off);
                int   ok = __shfl_xor_sync(0xffffffffu, bk, off);
                if (od < bd || (od == bd && ok < bk)) { bd = od; bk = ok; }
            }
            bi[rv] = bk;
        }

        if (t == 0) {
            #pragma unroll
            for (int rv = 0; rv < 4; ++rv) {
                const int row = base + (rv >> 1) * 16 + (rv & 1) * 8 + g;
                g_idx[row] = bi[rv];
                atomicAdd(&g_counts[bi[rv]], 1.0f);
            }
        }

        // scatter input sums: 32 rows x 64 dims
        #pragma unroll
        for (int r = 0; r < 32; ++r) {
            const int rv = r >> 3;
            int idx = __shfl_sync(0xffffffffu, bi[rv], (r & 7) * 4);
            const int row = base + (rv >> 1) * 16 + (rv & 1) * 8 + (r & 7);
            float va = X[(size_t)row * DDIM + lane];
            float vb = X[(size_t)row * DDIM + lane + 32];
            atomicAdd(&g_isum[idx * DDIM + lane], va);
            atomicAdd(&g_isum[idx * DDIM + lane + 32], vb);
        }
    }
}

// ---------------------------------------------------------------------------
// Kernel B1: EMA cluster sizes + inverse cluster size (1 block)
// ---------------------------------------------------------------------------
__global__ __launch_bounds__(1024) void k_ema_a(
        const float* __restrict__ ema_cs, float* __restrict__ out)
{
    __shared__ float red[1024];
    const int k = threadIdx.x;

    float ne = DECAY * ema_cs[k] + ONEMD * g_counts[k];
    out[OFF_ECS + k] = ne;

    red[k] = ne;
    __syncthreads();
    for (int s = 512; s > 0; s >>= 1) {
        if (k < s) red[k] += red[k + s];
        __syncthreads();
    }
    const float n = red[0];
    const float norm = (ne + EPS) / (n + (float)KCB * EPS);
    g_invcs[k] = 1.0f / (norm * n);
}

// Kernel B2: EMA input-sum + new codebook (elementwise)
__global__ __launch_bounds__(256) void k_ema_b(
        const float* __restrict__ ema_eis, float* __restrict__ out)
{
    int i = blockIdx.x * blockDim.x + threadIdx.x;
    int k = i & (KCB - 1);
    int d = i >> 10;
    float eis = DECAY * ema_eis[d * KCB + k] + ONEMD * g_isum[k * DDIM + d];
    out[OFF_EIS + d * KCB + k] = eis;
    float nc = eis * g_invcs[k];
    out[OFF_NCB + d * KCB + k] = nc;
    g_ncbT[k * DDIM + d] = nc;
}

// ---------------------------------------------------------------------------
// Kernel C: gather + straight-through + loss (float4, 2-way MLP)
// ---------------------------------------------------------------------------
__global__ __launch_bounds__(256) void k_gather_loss(
        const float* __restrict__ X, float* __restrict__ out)
{
    const int H = (N_ROWS * DDIM / 4) / 2;
    const int e0 = blockIdx.x * blockDim.x + threadIdx.x;
    const int e1 = e0 + H;
    const float4* X4 = reinterpret_cast<const float4*>(X);
    const float4* Q4 = reinterpret_cast<const float4*>(g_ncbT);
    float4* O4 = reinterpret_cast<float4*>(out + OFF_Q);

    int i0 = g_idx[e0 >> 4], i1 = g_idx[e1 >> 4];
    float4 x0 = X4[e0], x1 = X4[e1];
    float4 q0 = Q4[(i0 << 4) | (e0 & 15)];
    float4 q1 = Q4[(i1 << 4) | (e1 & 15)];

    float acc = 0.0f;
    float dx, dy, dz, dw;
    float4 o;
    dx = q0.x - x0.x; dy = q0.y - x0.y; dz = q0.z - x0.z; dw = q0.w - x0.w;
    o.x = x0.x + dx; o.y = x0.y + dy; o.z = x0.z + dz; o.w = x0.w + dw;
    O4[e0] = o;
    acc = fmaf(dx, dx, acc); acc = fmaf(dy, dy, acc);
    acc = fmaf(dz, dz, acc); acc = fmaf(dw, dw, acc);
    dx = q1.x - x1.x; dy = q1.y - x1.y; dz = q1.z - x1.z; dw = q1.w - x1.w;
    o.x = x1.x + dx; o.y = x1.y + dy; o.z = x1.z + dz; o.w = x1.w + dw;
    O4[e1] = o;
    acc = fmaf(dx, dx, acc); acc = fmaf(dy, dy, acc);
    acc = fmaf(dz, dz, acc); acc = fmaf(dw, dw, acc);

    #pragma unroll
    for (int o2 = 16; o2 > 0; o2 >>= 1)
        acc += __shfl_down_sync(0xffffffffu, acc, o2);
    __shared__ float warpsum[8];
    int lane = threadIdx.x & 31, wid = threadIdx.x >> 5;
    if (lane == 0) warpsum[wid] = acc;
    __syncthreads();
    if (wid == 0) {
        float vv = (lane < 8) ? warpsum[lane] : 0.0f;
        #pragma unroll
        for (int o2 = 4; o2 > 0; o2 >>= 1)
            vv += __shfl_down_sync(0xffffffffu, vv, o2);
        if (lane == 0) atomicAdd(g_loss, vv);
    }
}

__global__ void k_loss_finalize(float* __restrict__ out) {
    out[OFF_LOSS] = g_loss[0] * (1.0f / (float)(N_ROWS * DDIM));
}

// ---------------------------------------------------------------------------
extern "C" void kernel_launch(void* const* d_in, const int* in_sizes, int n_in,
                              void* d_out, int out_size) {
    const float* X       = (const float*)d_in[0];
    const float* CB      = (const float*)d_in[1];
    const float* EMA_CS  = (const float*)d_in[2];
    const float* EMA_EIS = (const float*)d_in[3];
    float* out = (float*)d_out;

    static const size_t dyn_smem = KCB * 4 + KCB * DDIM * 2;   // 4KB + 128KB
    cudaFuncSetAttribute(k_argmin_scatter,
                         cudaFuncAttributeMaxDynamicSharedMemorySize,
                         (int)dyn_smem);

    k_init_image<<<256, 256>>>(CB);                      // 0
    k_l2cb<<<16, 256>>>(CB);                             // 1
    k_argmin_scatter<<<GRID_A, 512, dyn_smem>>>(X, CB);  // 2
    k_ema_a<<<1, 1024>>>(EMA_CS, out);                   // 3
    k_ema_b<<<256, 256>>>(EMA_EIS, out);                 // 4
    k_gather_loss<<<4096, 256>>>(X, out);                // 5
    k_loss_finalize<<<1, 1>>>(out);                      // 6
}

// round 7
// speedup vs baseline: 1.8915x; 1.1280x over previous
#include <cuda_runtime.h>
#include <cuda_bf16.h>
#include <cstdint>

// Problem constants
#define N_ROWS   131072
#define DDIM     64
#define KCB      1024
#define DECAY    0.99f
#define ONEMD    0.01f
#define EPS      1e-5f
#define DELTA    0.6f        // window margin (>= 2x worst-case bf16 approx error)

#define NGROUPS  (N_ROWS / 32)   // 4096 warp work units
#define GRID_A   148

// Output layout
#define OFF_Q    0
#define OFF_LOSS (N_ROWS*DDIM)
#define OFF_NCB  (OFF_LOSS + 1)
#define OFF_ECS  (OFF_NCB + DDIM*KCB)
#define OFF_EIS  (OFF_ECS + KCB)

// Scratch
__device__ int            g_idx[N_ROWS];
__device__ float          g_counts[KCB];
__device__ float          g_isum[KCB * DDIM];     // [k][d], float4-aligned
__device__ float          g_l2cb[KCB];
__device__ float          g_invcs[KCB];
__device__ float          g_ncbT[KCB * DDIM];     // [k][d]
__device__ float          g_loss[1];
__device__ int            g_work;
__device__ __nv_bfloat16  g_cbbf[KCB * DDIM];     // fragment-major bf16 image (128KB)

// ---------------------------------------------------------------------------
__device__ __forceinline__ uint32_t packbf(float lo, float hi) {
    __nv_bfloat162 h = __floats2bfloat162_rn(lo, hi);
    return *reinterpret_cast<uint32_t*>(&h);
}

__device__ __forceinline__ void mma16(float c[4], const uint32_t a[4],
                                      uint32_t b0, uint32_t b1) {
    asm volatile(
        "mma.sync.aligned.m16n8k16.row.col.f32.bf16.bf16.f32 "
        "{%0,%1,%2,%3},{%4,%5,%6,%7},{%8,%9},{%0,%1,%2,%3};"
        : "+f"(c[0]), "+f"(c[1]), "+f"(c[2]), "+f"(c[3])
        : "r"(a[0]), "r"(a[1]), "r"(a[2]), "r"(a[3]), "r"(b0), "r"(b1));
}

__device__ __forceinline__ void cp_async16(uint32_t smem_dst, const void* gsrc) {
    asm volatile("cp.async.cg.shared.global [%0], [%1], 16;"
                 :: "r"(smem_dst), "l"(gsrc));
}

// exact reduced score (l2cb - 2*dot), fp32, 4 accumulators
__device__ __forceinline__ float exact_sc(const float* __restrict__ X,
                                          const float* __restrict__ CB,
                                          const float* __restrict__ s_l2,
                                          int row, int k) {
    const float4* xr = reinterpret_cast<const float4*>(X + (size_t)row * DDIM);
    float a0 = 0.f, a1 = 0.f, a2 = 0.f, a3 = 0.f;
    #pragma unroll
    for (int jj = 0; jj < 16; ++jj) {
        float4 xv = xr[jj];
        a0 = fmaf(xv.x, CB[(4 * jj + 0) * KCB + k], a0);
        a1 = fmaf(xv.y, CB[(4 * jj + 1) * KCB + k], a1);
        a2 = fmaf(xv.z, CB[(4 * jj + 2) * KCB + k], a2);
        a3 = fmaf(xv.w, CB[(4 * jj + 3) * KCB + k], a3);
    }
    return fmaf(-2.f, (a0 + a1) + (a2 + a3), s_l2[k]);
}

// ---------------------------------------------------------------------------
// Kernel 0: zero g_isum + build fragment-major bf16 codebook image
// ---------------------------------------------------------------------------
__global__ void k_init_image(const float* __restrict__ cb) {
    int i = blockIdx.x * blockDim.x + threadIdx.x;   // 0..65535
    int n = i & (KCB - 1);
    int d = i >> 10;

    g_isum[i] = 0.0f;

    float x = cb[d * KCB + n];
    int tt = n >> 6, nl = n & 63;
    int nb = nl >> 3, g = nl & 7;
    int ks = d >> 4, dk = d & 15;
    int t = (dk >> 1) & 3, reg = dk >> 3, half = dk & 1;
    int lane = g * 4 + t;
    int u32idx = ((tt * 32) + ks * 8 + nb) * 64 + lane * 2 + reg;
    g_cbbf[u32idx * 2 + half] = __float2bfloat16_rn(x);
}

// Kernel 1: ||c_k||^2 + small zeroing
__global__ void k_l2cb(const float* __restrict__ cb) {
    __shared__ float part[256];
    int nl = threadIdx.x & 63, dq = threadIdx.x >> 6;
    int n = blockIdx.x * 64 + nl;
    float s = 0.0f;
    #pragma unroll
    for (int j = 0; j < 16; ++j) {
        float c = cb[(dq * 16 + j) * KCB + n];
        s = fmaf(c, c, s);
    }
    part[threadIdx.x] = s;
    __syncthreads();
    if (dq == 0)
        g_l2cb[n] = (part[nl] + part[64 + nl]) + (part[128 + nl] + part[192 + nl]);
    if (blockIdx.x == 0) {
        int i = threadIdx.x;
        g_counts[i] = 0.f; g_counts[i+256] = 0.f;
        g_counts[i+512] = 0.f; g_counts[i+768] = 0.f;
        if (i == 0) { g_loss[0] = 0.0f; g_work = 0; }
    }
}

// ---------------------------------------------------------------------------
// Kernel A: two-pass bf16 tensor argmin + exact rescore + vector-atomic scatter
// ---------------------------------------------------------------------------
extern __shared__ float s_dyn[];

#define INS(RV, S, COL) do { if ((S) < th[RV]) {          \
      if      (cnt[RV] == 0) cand[RV][0] = (COL);          \
      else if (cnt[RV] == 1) cand[RV][1] = (COL);          \
      else if (cnt[RV] == 2) cand[RV][2] = (COL);          \
      else if (cnt[RV] == 3) cand[RV][3] = (COL);          \
      cnt[RV]++; } } while (0)

__global__ __launch_bounds__(512, 1) void k_argmin_scatter(
        const float* __restrict__ X, const float* __restrict__ CB)
{
    float*    s_l2 = s_dyn;                                    // 1024 floats
    uint32_t* s_cb = reinterpret_cast<uint32_t*>(s_dyn + KCB); // 32768 u32

    const int tid  = threadIdx.x;
    const int lane = tid & 31;
    const int g    = lane >> 2;
    const int t    = lane & 3;

    for (int i = tid; i < KCB; i += 512) s_l2[i] = g_l2cb[i];
    {
        const uint32_t sb = (uint32_t)__cvta_generic_to_shared(s_cb);
        const float4* src = reinterpret_cast<const float4*>(g_cbbf);
        #pragma unroll
        for (int j = 0; j < 16; ++j) {
            int e = tid + j * 512;
            cp_async16(sb + e * 16, src + e);
        }
        asm volatile("cp.async.commit_group;");
        asm volatile("cp.async.wait_group 0;");
    }
    __syncthreads();

    const float INF = __int_as_float(0x7f800000);

    for (;;) {
        int gid = 0;
        if (lane == 0) gid = atomicAdd(&g_work, 1);
        gid = __shfl_sync(0xffffffffu, gid, 0);
        if (gid >= NGROUPS) break;

        const int base = gid * 32;

        // A fragments (bf16), 2 m-tiles = 32 rows (rows base..base+31)
        uint32_t Ah[2][4][4];
        #pragma unroll
        for (int m = 0; m < 2; ++m) {
            const float* xa = X + (size_t)(base + m * 16 + g) * DDIM;
            const float* xb = xa + 8 * DDIM;
            #pragma unroll
            for (int ks = 0; ks < 4; ++ks) {
                int ci = ks * 16 + 2 * t;
                Ah[m][ks][0] = packbf(xa[ci],     xa[ci + 1]);
                Ah[m][ks][1] = packbf(xb[ci],     xb[ci + 1]);
                Ah[m][ks][2] = packbf(xa[ci + 8], xa[ci + 9]);
                Ah[m][ks][3] = packbf(xb[ci + 8], xb[ci + 9]);
            }
        }

        // ---------------- pass 1: min only ----------------
        float mn[4] = {INF, INF, INF, INF};
        #pragma unroll 2
        for (int tt = 0; tt < 16; ++tt) {
            #pragma unroll
            for (int nb = 0; nb < 8; ++nb) {
                float c0[4] = {0.f, 0.f, 0.f, 0.f};
                float c1[4] = {0.f, 0.f, 0.f, 0.f};
                #pragma unroll
                for (int ks = 0; ks < 4; ++ks) {
                    uint2 bp = *reinterpret_cast<const uint2*>(
                        &s_cb[((tt * 32) + ks * 8 + nb) * 64 + lane * 2]);
                    mma16(c0, Ah[0][ks], bp.x, bp.y);
                    mma16(c1, Ah[1][ks], bp.x, bp.y);
                }
                float2 l2p = *reinterpret_cast<const float2*>(
                    &s_l2[tt * 64 + nb * 8 + 2 * t]);
                mn[0] = fminf(mn[0], fmaf(-2.f, c0[0], l2p.x));
                mn[0] = fminf(mn[0], fmaf(-2.f, c0[1], l2p.y));
                mn[1] = fminf(mn[1], fmaf(-2.f, c0[2], l2p.x));
                mn[1] = fminf(mn[1], fmaf(-2.f, c0[3], l2p.y));
                mn[2] = fminf(mn[2], fmaf(-2.f, c1[0], l2p.x));
                mn[2] = fminf(mn[2], fmaf(-2.f, c1[1], l2p.y));
                mn[3] = fminf(mn[3], fmaf(-2.f, c1[2], l2p.x));
                mn[3] = fminf(mn[3], fmaf(-2.f, c1[3], l2p.y));
            }
        }

        float th[4];
        #pragma unroll
        for (int rv = 0; rv < 4; ++rv) {
            float m = mn[rv];
            m = fminf(m, __shfl_xor_sync(0xffffffffu, m, 1));
            m = fminf(m, __shfl_xor_sync(0xffffffffu, m, 2));
            th[rv] = m + DELTA;
        }

        // ---------------- pass 2: collect candidates (rare-branch) ---------
        int cnt[4] = {0, 0, 0, 0};
        int cand[4][4];
        #pragma unroll
        for (int rv = 0; rv < 4; ++rv) {
            cand[rv][0] = cand[rv][1] = cand[rv][2] = cand[rv][3] = 0;
        }

        #pragma unroll 2
        for (int tt = 0; tt < 16; ++tt) {
            #pragma unroll
            for (int nb = 0; nb < 8; ++nb) {
                float c0[4] = {0.f, 0.f, 0.f, 0.f};
                float c1[4] = {0.f, 0.f, 0.f, 0.f};
                #pragma unroll
                for (int ks = 0; ks < 4; ++ks) {
                    uint2 bp = *reinterpret_cast<const uint2*>(
                        &s_cb[((tt * 32) + ks * 8 + nb) * 64 + lane * 2]);
                    mma16(c0, Ah[0][ks], bp.x, bp.y);
                    mma16(c1, Ah[1][ks], bp.x, bp.y);
                }
                const int colb = tt * 64 + nb * 8 + 2 * t;
                float2 l2p = *reinterpret_cast<const float2*>(&s_l2[colb]);
                float s0 = fmaf(-2.f, c0[0], l2p.x);
                float s1 = fmaf(-2.f, c0[1], l2p.y);
                float s2 = fmaf(-2.f, c0[2], l2p.x);
                float s3 = fmaf(-2.f, c0[3], l2p.y);
                float s4 = fmaf(-2.f, c1[0], l2p.x);
                float s5 = fmaf(-2.f, c1[1], l2p.y);
                float s6 = fmaf(-2.f, c1[2], l2p.x);
                float s7 = fmaf(-2.f, c1[3], l2p.y);
                // cheap screen: pairwise mins vs per-row thresholds
                bool hit = (fminf(s0, s1) < th[0]) | (fminf(s2, s3) < th[1])
                         | (fminf(s4, s5) < th[2]) | (fminf(s6, s7) < th[3]);
                if (hit) {
                    INS(0, s0, colb); INS(0, s1, colb + 1);
                    INS(1, s2, colb); INS(1, s3, colb + 1);
                    INS(2, s4, colb); INS(2, s5, colb + 1);
                    INS(3, s6, colb); INS(3, s7, colb + 1);
                }
            }
        }

        // ---------------- exact rescore of candidates ----------------
        int bi[4];
        #pragma unroll
        for (int rv = 0; rv < 4; ++rv) {
            const int row = base + rv * 8 + g;
            float bd = INF;
            int   bk = 0x7fffffff;
            #pragma unroll
            for (int sl = 0; sl < 4; ++sl) {
                if (sl < cnt[rv]) {
                    int k = cand[rv][sl];
                    float d = exact_sc(X, CB, s_l2, row, k);
                    if (d < bd || (d == bd && k < bk)) { bd = d; bk = k; }
                }
            }
            #pragma unroll
            for (int off = 1; off < 4; off <<= 1) {
                float od = __shfl_xor_sync(0xffffffffu, bd, off);
                int   ok = __shfl_xor_sync(0xffffffffu, bk, off);
                if (od < bd || (od == bd && ok < bk)) { bd = od; bk = ok; }
            }
            bi[rv] = bk;
        }

        if (t == 0) {
            #pragma unroll
            for (int rv = 0; rv < 4; ++rv) {
                g_idx[base + rv * 8 + g] = bi[rv];
                atomicAdd(&g_counts[bi[rv]], 1.0f);
            }
        }

        // scatter input sums: float4 vector atomics, 2 rows per iteration
        const float4* X4 = reinterpret_cast<const float4*>(X);
        #pragma unroll
        for (int rr = 0; rr < 32; rr += 2) {
            int r   = rr + (lane >> 4);              // row offset within group
            int src = ((rr & 7) + (lane >> 4)) * 4;  // lane holding bi for row r
            int idx = __shfl_sync(0xffffffffu, bi[rr >> 3], src);
            float4 v = X4[(size_t)(base + r) * 16 + (lane & 15)];
            atomicAdd(reinterpret_cast<float4*>(g_isum + idx * DDIM) + (lane & 15), v);
        }
    }
}

// ---------------------------------------------------------------------------
// Kernel B1: EMA cluster sizes + inverse cluster size (1 block)
// ---------------------------------------------------------------------------
__global__ __launch_bounds__(1024) void k_ema_a(
        const float* __restrict__ ema_cs, float* __restrict__ out)
{
    __shared__ float red[1024];
    const int k = threadIdx.x;

    float ne = DECAY * ema_cs[k] + ONEMD * g_counts[k];
    out[OFF_ECS + k] = ne;

    red[k] = ne;
    __syncthreads();
    for (int s = 512; s > 0; s >>= 1) {
        if (k < s) red[k] += red[k + s];
        __syncthreads();
    }
    const float n = red[0];
    const float norm = (ne + EPS) / (n + (float)KCB * EPS);
    g_invcs[k] = 1.0f / (norm * n);
}

// Kernel B2: EMA input-sum + new codebook (elementwise)
__global__ __launch_bounds__(256) void k_ema_b(
        const float* __restrict__ ema_eis, float* __restrict__ out)
{
    int i = blockIdx.x * blockDim.x + threadIdx.x;
    int k = i & (KCB - 1);
    int d = i >> 10;
    float eis = DECAY * ema_eis[d * KCB + k] + ONEMD * g_isum[k * DDIM + d];
    out[OFF_EIS + d * KCB + k] = eis;
    float nc = eis * g_invcs[k];
    out[OFF_NCB + d * KCB + k] = nc;
    g_ncbT[k * DDIM + d] = nc;
}

// ---------------------------------------------------------------------------
// Kernel C: gather + straight-through + loss (float4, 2-way MLP)
// ---------------------------------------------------------------------------
__global__ __launch_bounds__(256) void k_gather_loss(
        const float* __restrict__ X, float* __restrict__ out)
{
    const int H = (N_ROWS * DDIM / 4) / 2;
    const int e0 = blockIdx.x * blockDim.x + threadIdx.x;
    const int e1 = e0 + H;
    const float4* X4 = reinterpret_cast<const float4*>(X);
    const float4* Q4 = reinterpret_cast<const float4*>(g_ncbT);
    float4* O4 = reinterpret_cast<float4*>(out + OFF_Q);

    int i0 = g_idx[e0 >> 4], i1 = g_idx[e1 >> 4];
    float4 x0 = X4[e0], x1 = X4[e1];
    float4 q0 = Q4[(i0 << 4) | (e0 & 15)];
    float4 q1 = Q4[(i1 << 4) | (e1 & 15)];

    float acc = 0.0f;
    float dx, dy, dz, dw;
    float4 o;
    dx = q0.x - x0.x; dy = q0.y - x0.y; dz = q0.z - x0.z; dw = q0.w - x0.w;
    o.x = x0.x + dx; o.y = x0.y + dy; o.z = x0.z + dz; o.w = x0.w + dw;
    O4[e0] = o;
    acc = fmaf(dx, dx, acc); acc = fmaf(dy, dy, acc);
    acc = fmaf(dz, dz, acc); acc = fmaf(dw, dw, acc);
    dx = q1.x - x1.x; dy = q1.y - x1.y; dz = q1.z - x1.z; dw = q1.w - x1.w;
    o.x = x1.x + dx; o.y = x1.y + dy; o.z = x1.z + dz; o.w = x1.w + dw;
    O4[e1] = o;
    acc = fmaf(dx, dx, acc); acc = fmaf(dy, dy, acc);
    acc = fmaf(dz, dz, acc); acc = fmaf(dw, dw, acc);

    #pragma unroll
    for (int o2 = 16; o2 > 0; o2 >>= 1)
        acc += __shfl_down_sync(0xffffffffu, acc, o2);
    __shared__ float warpsum[8];
    int lane = threadIdx.x & 31, wid = threadIdx.x >> 5;
    if (lane == 0) warpsum[wid] = acc;
    __syncthreads();
    if (wid == 0) {
        float vv = (lane < 8) ? warpsum[lane] : 0.0f;
        #pragma unroll
        for (int o2 = 4; o2 > 0; o2 >>= 1)
            vv += __shfl_down_sync(0xffffffffu, vv, o2);
        if (lane == 0) atomicAdd(g_loss, vv);
    }
}

__global__ void k_loss_finalize(float* __restrict__ out) {
    out[OFF_LOSS] = g_loss[0] * (1.0f / (float)(N_ROWS * DDIM));
}

// ---------------------------------------------------------------------------
extern "C" void kernel_launch(void* const* d_in, const int* in_sizes, int n_in,
                              void* d_out, int out_size) {
    const float* X       = (const float*)d_in[0];
    const float* CB      = (const float*)d_in[1];
    const float* EMA_CS  = (const float*)d_in[2];
    const float* EMA_EIS = (const float*)d_in[3];
    float* out = (float*)d_out;

    static const size_t dyn_smem = KCB * 4 + KCB * DDIM * 2;   // 4KB + 128KB
    cudaFuncSetAttribute(k_argmin_scatter,
                         cudaFuncAttributeMaxDynamicSharedMemorySize,
                         (int)dyn_smem);

    k_init_image<<<256, 256>>>(CB);                      // 0
    k_l2cb<<<16, 256>>>(CB);                             // 1
    k_argmin_scatter<<<GRID_A, 512, dyn_smem>>>(X, CB);  // 2
    k_ema_a<<<1, 1024>>>(EMA_CS, out);                   // 3
    k_ema_b<<<256, 256>>>(EMA_EIS, out);                 // 4
    k_gather_loss<<<4096, 256>>>(X, out);                // 5
    k_loss_finalize<<<1, 1>>>(out);                      // 6
}

// round 8
// speedup vs baseline: 2.7077x; 1.4315x over previous
#include <cuda_runtime.h>
#include <cuda_bf16.h>
#include <cstdint>

// Problem constants
#define N_ROWS   131072
#define DDIM     64
#define KCB      1024
#define DECAY    0.99f
#define ONEMD    0.01f
#define EPS      1e-5f
#define BIAS     512.0f      // makes all reduced scores positive (min > -280)
#define WINDOW   0.7f        // rescore window: bf16 err bound + truncation fuzz

#define NGROUPS  (N_ROWS / 32)   // 4096 warp work units
#define GRID_A   148

// Output layout
#define OFF_Q    0
#define OFF_LOSS (N_ROWS*DDIM)
#define OFF_NCB  (OFF_LOSS + 1)
#define OFF_ECS  (OFF_NCB + DDIM*KCB)
#define OFF_EIS  (OFF_ECS + KCB)

// Scratch
__device__ int            g_idx[N_ROWS];
__device__ float          g_counts[KCB];
__device__ float          g_isum[KCB * DDIM];     // [k][d]
__device__ float          g_l2cb[KCB];
__device__ float          g_invcs[KCB];
__device__ float          g_ncbT[KCB * DDIM];     // [k][d]
__device__ float          g_loss[1];
__device__ int            g_work;
__device__ __nv_bfloat16  g_cbbf[KCB * DDIM];     // fragment-major bf16 image (128KB)

// ---------------------------------------------------------------------------
__device__ __forceinline__ uint32_t packbf(float lo, float hi) {
    __nv_bfloat162 h = __floats2bfloat162_rn(lo, hi);
    return *reinterpret_cast<uint32_t*>(&h);
}

__device__ __forceinline__ void mma16(float c[4], const uint32_t a[4],
                                      uint32_t b0, uint32_t b1) {
    asm volatile(
        "mma.sync.aligned.m16n8k16.row.col.f32.bf16.bf16.f32 "
        "{%0,%1,%2,%3},{%4,%5,%6,%7},{%8,%9},{%0,%1,%2,%3};"
        : "+f"(c[0]), "+f"(c[1]), "+f"(c[2]), "+f"(c[3])
        : "r"(a[0]), "r"(a[1]), "r"(a[2]), "r"(a[3]), "r"(b0), "r"(b1));
}

__device__ __forceinline__ void cp_async16(uint32_t smem_dst, const void* gsrc) {
    asm volatile("cp.async.cg.shared.global [%0], [%1], 16;"
                 :: "r"(smem_dst), "l"(gsrc));
}

// sorted top-3 insert of packed (score|col), ascending; 5 IMNMX
__device__ __forceinline__ void top3(uint32_t p, uint32_t v[3]) {
    uint32_t a = max(v[0], p); v[0] = min(v[0], p);
    uint32_t b = max(v[1], a); v[1] = min(v[1], a);
    v[2] = min(v[2], b);
}

// biased exact reduced score (bias cancels in comparisons)
__device__ __forceinline__ float exact_sc(const float* __restrict__ X,
                                          const float* __restrict__ CB,
                                          const float* __restrict__ s_l2b,
                                          int row, int k) {
    const float4* xr = reinterpret_cast<const float4*>(X + (size_t)row * DDIM);
    float a0 = 0.f, a1 = 0.f, a2 = 0.f, a3 = 0.f;
    #pragma unroll
    for (int jj = 0; jj < 16; ++jj) {
        float4 xv = xr[jj];
        a0 = fmaf(xv.x, CB[(4 * jj + 0) * KCB + k], a0);
        a1 = fmaf(xv.y, CB[(4 * jj + 1) * KCB + k], a1);
        a2 = fmaf(xv.z, CB[(4 * jj + 2) * KCB + k], a2);
        a3 = fmaf(xv.w, CB[(4 * jj + 3) * KCB + k], a3);
    }
    return fmaf(-2.f, (a0 + a1) + (a2 + a3), s_l2b[k]);
}

// ---------------------------------------------------------------------------
// Kernel 0: zero g_isum + build fragment-major bf16 codebook image
// ---------------------------------------------------------------------------
__global__ void k_init_image(const float* __restrict__ cb) {
    int i = blockIdx.x * blockDim.x + threadIdx.x;   // 0..65535
    int n = i & (KCB - 1);
    int d = i >> 10;

    g_isum[i] = 0.0f;

    float x = cb[d * KCB + n];
    int tt = n >> 6, nl = n & 63;
    int nb = nl >> 3, g = nl & 7;
    int ks = d >> 4, dk = d & 15;
    int t = (dk >> 1) & 3, reg = dk >> 3, half = dk & 1;
    int lane = g * 4 + t;
    int u32idx = ((tt * 32) + ks * 8 + nb) * 64 + lane * 2 + reg;
    g_cbbf[u32idx * 2 + half] = __float2bfloat16_rn(x);
}

// Kernel 1: ||c_k||^2 + small zeroing
__global__ void k_l2cb(const float* __restrict__ cb) {
    __shared__ float part[256];
    int nl = threadIdx.x & 63, dq = threadIdx.x >> 6;
    int n = blockIdx.x * 64 + nl;
    float s = 0.0f;
    #pragma unroll
    for (int j = 0; j < 16; ++j) {
        float c = cb[(dq * 16 + j) * KCB + n];
        s = fmaf(c, c, s);
    }
    part[threadIdx.x] = s;
    __syncthreads();
    if (dq == 0)
        g_l2cb[n] = (part[nl] + part[64 + nl]) + (part[128 + nl] + part[192 + nl]);
    if (blockIdx.x == 0) {
        int i = threadIdx.x;
        g_counts[i] = 0.f; g_counts[i+256] = 0.f;
        g_counts[i+512] = 0.f; g_counts[i+768] = 0.f;
        if (i == 0) { g_loss[0] = 0.0f; g_work = 0; }
    }
}

// ---------------------------------------------------------------------------
// Kernel A: single-pass bf16 tensor argmin (packed top-3) + exact rescore +
// vector-atomic scatter.
// ---------------------------------------------------------------------------
extern __shared__ float s_dyn[];

__global__ __launch_bounds__(512, 1) void k_argmin_scatter(
        const float* __restrict__ X, const float* __restrict__ CB)
{
    float*    s_l2 = s_dyn;                                    // 1024 floats (biased)
    uint32_t* s_cb = reinterpret_cast<uint32_t*>(s_dyn + KCB); // 32768 u32

    const int tid  = threadIdx.x;
    const int lane = tid & 31;
    const int g    = lane >> 2;
    const int t    = lane & 3;

    for (int i = tid; i < KCB; i += 512) s_l2[i] = g_l2cb[i] + BIAS;
    {
        const uint32_t sb = (uint32_t)__cvta_generic_to_shared(s_cb);
        const float4* src = reinterpret_cast<const float4*>(g_cbbf);
        #pragma unroll
        for (int j = 0; j < 16; ++j) {
            int e = tid + j * 512;
            cp_async16(sb + e * 16, src + e);
        }
        asm volatile("cp.async.commit_group;");
        asm volatile("cp.async.wait_group 0;");
    }
    __syncthreads();

    const float INF = __int_as_float(0x7f800000);

    for (;;) {
        int gid = 0;
        if (lane == 0) gid = atomicAdd(&g_work, 1);
        gid = __shfl_sync(0xffffffffu, gid, 0);
        if (gid >= NGROUPS) break;

        const int base = gid * 32;

        // A fragments (bf16), 2 m-tiles = 32 rows
        uint32_t Ah[2][4][4];
        #pragma unroll
        for (int m = 0; m < 2; ++m) {
            const float* xa = X + (size_t)(base + m * 16 + g) * DDIM;
            const float* xb = xa + 8 * DDIM;
            #pragma unroll
            for (int ks = 0; ks < 4; ++ks) {
                int ci = ks * 16 + 2 * t;
                Ah[m][ks][0] = packbf(xa[ci],     xa[ci + 1]);
                Ah[m][ks][1] = packbf(xb[ci],     xb[ci + 1]);
                Ah[m][ks][2] = packbf(xa[ci + 8], xa[ci + 9]);
                Ah[m][ks][3] = packbf(xb[ci + 8], xb[ci + 9]);
            }
        }

        // packed top-3 per row-var (rv = rows base + rv*8 + g)
        uint32_t v[4][3];
        #pragma unroll
        for (int rv = 0; rv < 4; ++rv)
            v[rv][0] = v[rv][1] = v[rv][2] = 0xFFFFFFFFu;

        #pragma unroll 2
        for (int tt = 0; tt < 16; ++tt) {
            #pragma unroll
            for (int nb = 0; nb < 8; ++nb) {
                float c0[4] = {0.f, 0.f, 0.f, 0.f};
                float c1[4] = {0.f, 0.f, 0.f, 0.f};
                #pragma unroll
                for (int ks = 0; ks < 4; ++ks) {
                    uint2 bp = *reinterpret_cast<const uint2*>(
                        &s_cb[((tt * 32) + ks * 8 + nb) * 64 + lane * 2]);
                    mma16(c0, Ah[0][ks], bp.x, bp.y);
                    mma16(c1, Ah[1][ks], bp.x, bp.y);
                }
                const uint32_t colb = tt * 64 + nb * 8 + 2 * t;
                float2 l2p = *reinterpret_cast<const float2*>(&s_l2[colb]);
                // biased positive scores -> float bits are order-monotone
                uint32_t p;
                p = (__float_as_uint(fmaf(-2.f, c0[0], l2p.x)) & 0xFFFFFC00u) | colb;
                top3(p, v[0]);
                p = (__float_as_uint(fmaf(-2.f, c0[1], l2p.y)) & 0xFFFFFC00u) | (colb + 1);
                top3(p, v[0]);
                p = (__float_as_uint(fmaf(-2.f, c0[2], l2p.x)) & 0xFFFFFC00u) | colb;
                top3(p, v[1]);
                p = (__float_as_uint(fmaf(-2.f, c0[3], l2p.y)) & 0xFFFFFC00u) | (colb + 1);
                top3(p, v[1]);
                p = (__float_as_uint(fmaf(-2.f, c1[0], l2p.x)) & 0xFFFFFC00u) | colb;
                top3(p, v[2]);
                p = (__float_as_uint(fmaf(-2.f, c1[1], l2p.y)) & 0xFFFFFC00u) | (colb + 1);
                top3(p, v[2]);
                p = (__float_as_uint(fmaf(-2.f, c1[2], l2p.x)) & 0xFFFFFC00u) | colb;
                top3(p, v[3]);
                p = (__float_as_uint(fmaf(-2.f, c1[3], l2p.y)) & 0xFFFFFC00u) | (colb + 1);
                top3(p, v[3]);
            }
        }

        // exact rescore of windowed candidates
        int bi[4];
        #pragma unroll
        for (int rv = 0; rv < 4; ++rv) {
            uint32_t m = v[rv][0];
            m = min(m, __shfl_xor_sync(0xffffffffu, m, 1));
            m = min(m, __shfl_xor_sync(0xffffffffu, m, 2));
            const float thr = __uint_as_float(m & 0xFFFFFC00u) + WINDOW;

            const int row = base + rv * 8 + g;
            float bd = INF;
            int   bk = 0x7fffffff;
            #pragma unroll
            for (int sl = 0; sl < 3; ++sl) {
                uint32_t p = v[rv][sl];
                if (__uint_as_float(p & 0xFFFFFC00u) <= thr) {
                    int k = (int)(p & 0x3FFu);
                    float d = exact_sc(X, CB, s_l2, row, k);
                    if (d < bd || (d == bd && k < bk)) { bd = d; bk = k; }
                }
            }
            #pragma unroll
            for (int off = 1; off < 4; off <<= 1) {
                float od = __shfl_xor_sync(0xffffffffu, bd, off);
                int   ok = __shfl_xor_sync(0xffffffffu, bk, off);
                if (od < bd || (od == bd && ok < bk)) { bd = od; bk = ok; }
            }
            bi[rv] = bk;
        }

        if (t == 0) {
            #pragma unroll
            for (int rv = 0; rv < 4; ++rv) {
                g_idx[base + rv * 8 + g] = bi[rv];
                atomicAdd(&g_counts[bi[rv]], 1.0f);
            }
        }

        // scatter input sums: float4 vector atomics, 2 rows per iteration
        const float4* X4 = reinterpret_cast<const float4*>(X);
        #pragma unroll
        for (int rr = 0; rr < 32; rr += 2) {
            int r   = rr + (lane >> 4);
            int src = ((rr & 7) + (lane >> 4)) * 4;
            int idx = __shfl_sync(0xffffffffu, bi[rr >> 3], src);
            float4 vv = X4[(size_t)(base + r) * 16 + (lane & 15)];
            atomicAdd(reinterpret_cast<float4*>(g_isum + idx * DDIM) + (lane & 15), vv);
        }
    }
}

// ---------------------------------------------------------------------------
// Kernel B1: EMA cluster sizes + inverse cluster size (1 block, shfl reduce)
// ---------------------------------------------------------------------------
__global__ __launch_bounds__(1024) void k_ema_a(
        const float* __restrict__ ema_cs, float* __restrict__ out)
{
    __shared__ float warps[32];
    const int k = threadIdx.x;
    const int lane = k & 31, wid = k >> 5;

    float ne = DECAY * ema_cs[k] + ONEMD * g_counts[k];
    out[OFF_ECS + k] = ne;

    float s = ne;
    #pragma unroll
    for (int o = 16; o > 0; o >>= 1)
        s += __shfl_down_sync(0xffffffffu, s, o);
    if (lane == 0) warps[wid] = s;
    __syncthreads();
    float n;
    {
        float w = warps[lane];
        #pragma unroll
        for (int o = 16; o > 0; o >>= 1)
            w += __shfl_xor_sync(0xffffffffu, w, o);
        n = w;
    }

    const float norm = (ne + EPS) / (n + (float)KCB * EPS);
    g_invcs[k] = 1.0f / (norm * n);
}

// Kernel B2: EMA input-sum + new codebook (elementwise)
__global__ __launch_bounds__(256) void k_ema_b(
        const float* __restrict__ ema_eis, float* __restrict__ out)
{
    int i = blockIdx.x * blockDim.x + threadIdx.x;
    int k = i & (KCB - 1);
    int d = i >> 10;
    float eis = DECAY * ema_eis[d * KCB + k] + ONEMD * g_isum[k * DDIM + d];
    out[OFF_EIS + d * KCB + k] = eis;
    float nc = eis * g_invcs[k];
    out[OFF_NCB + d * KCB + k] = nc;
    g_ncbT[k * DDIM + d] = nc;
}

// ---------------------------------------------------------------------------
// Kernel C: gather + straight-through + loss (float4, 2-way MLP)
// ---------------------------------------------------------------------------
__global__ __launch_bounds__(256) void k_gather_loss(
        const float* __restrict__ X, float* __restrict__ out)
{
    const int H = (N_ROWS * DDIM / 4) / 2;
    const int e0 = blockIdx.x * blockDim.x + threadIdx.x;
    const int e1 = e0 + H;
    const float4* X4 = reinterpret_cast<const float4*>(X);
    const float4* Q4 = reinterpret_cast<const float4*>(g_ncbT);
    float4* O4 = reinterpret_cast<float4*>(out + OFF_Q);

    int i0 = g_idx[e0 >> 4], i1 = g_idx[e1 >> 4];
    float4 x0 = X4[e0], x1 = X4[e1];
    float4 q0 = Q4[(i0 << 4) | (e0 & 15)];
    float4 q1 = Q4[(i1 << 4) | (e1 & 15)];

    float acc = 0.0f;
    float dx, dy, dz, dw;
    float4 o;
    dx = q0.x - x0.x; dy = q0.y - x0.y; dz = q0.z - x0.z; dw = q0.w - x0.w;
    o.x = x0.x + dx; o.y = x0.y + dy; o.z = x0.z + dz; o.w = x0.w + dw;
    O4[e0] = o;
    acc = fmaf(dx, dx, acc); acc = fmaf(dy, dy, acc);
    acc = fmaf(dz, dz, acc); acc = fmaf(dw, dw, acc);
    dx = q1.x - x1.x; dy = q1.y - x1.y; dz = q1.z - x1.z; dw = q1.w - x1.w;
    o.x = x1.x + dx; o.y = x1.y + dy; o.z = x1.z + dz; o.w = x1.w + dw;
    O4[e1] = o;
    acc = fmaf(dx, dx, acc); acc = fmaf(dy, dy, acc);
    acc = fmaf(dz, dz, acc); acc = fmaf(dw, dw, acc);

    #pragma unroll
    for (int o2 = 16; o2 > 0; o2 >>= 1)
        acc += __shfl_down_sync(0xffffffffu, acc, o2);
    __shared__ float warpsum[8];
    int lane = threadIdx.x & 31, wid = threadIdx.x >> 5;
    if (lane == 0) warpsum[wid] = acc;
    __syncthreads();
    if (wid == 0) {
        float vv = (lane < 8) ? warpsum[lane] : 0.0f;
        #pragma unroll
        for (int o2 = 4; o2 > 0; o2 >>= 1)
            vv += __shfl_down_sync(0xffffffffu, vv, o2);
        if (lane == 0) atomicAdd(g_loss, vv);
    }
}

__global__ void k_loss_finalize(float* __restrict__ out) {
    out[OFF_LOSS] = g_loss[0] * (1.0f / (float)(N_ROWS * DDIM));
}

// ---------------------------------------------------------------------------
extern "C" void kernel_launch(void* const* d_in, const int* in_sizes, int n_in,
                              void* d_out, int out_size) {
    const float* X       = (const float*)d_in[0];
    const float* CB      = (const float*)d_in[1];
    const float* EMA_CS  = (const float*)d_in[2];
    const float* EMA_EIS = (const float*)d_in[3];
    float* out = (float*)d_out;

    static const size_t dyn_smem = KCB * 4 + KCB * DDIM * 2;   // 4KB + 128KB
    cudaFuncSetAttribute(k_argmin_scatter,
                         cudaFuncAttributeMaxDynamicSharedMemorySize,
                         (int)dyn_smem);

    k_init_image<<<256, 256>>>(CB);                      // 0
    k_l2cb<<<16, 256>>>(CB);                             // 1
    k_argmin_scatter<<<GRID_A, 512, dyn_smem>>>(X, CB);  // 2
    k_ema_a<<<1, 1024>>>(EMA_CS, out);                   // 3
    k_ema_b<<<256, 256>>>(EMA_EIS, out);                 // 4
    k_gather_loss<<<4096, 256>>>(X, out);                // 5
    k_loss_finalize<<<1, 1>>>(out);                      // 6
}